// round 1
// baseline (speedup 1.0000x reference)
#include <cuda_runtime.h>
#include <mma.h>

using namespace nvcuda;

#define B_   2
#define S_   2048
#define H_   16
#define D_   64
#define HID  1024
#define MROWS (B_*S_)          // 4096

#define QB 64
#define TB 128
#define NCH (S_/TB)            // 16

// ---------------- scratch (static device memory; no allocations) ----------
__device__ float g_q[(size_t)B_*H_*S_*D_];
__device__ float g_k[(size_t)B_*H_*S_*D_];
__device__ float g_v[(size_t)B_*H_*S_*D_];
__device__ float g_concat[(size_t)MROWS*HID];

// ---------------- tf32 split helper (fp32-accurate 3-term MMA) ------------
template <typename FragT>
__device__ __forceinline__ void split_tf32(FragT& hi, FragT& lo, const FragT& raw) {
#pragma unroll
    for (int i = 0; i < raw.num_elements; i++) {
        float h = wmma::__float_to_tf32(raw.x[i]);
        hi.x[i] = h;
        lo.x[i] = wmma::__float_to_tf32(raw.x[i] - h);
    }
}

typedef wmma::fragment<wmma::matrix_a, 16, 16, 8, wmma::precision::tf32, wmma::row_major> AFrag;
typedef wmma::fragment<wmma::matrix_b, 16, 16, 8, wmma::precision::tf32, wmma::row_major> BFragR;
typedef wmma::fragment<wmma::matrix_b, 16, 16, 8, wmma::precision::tf32, wmma::col_major> BFragC;
typedef wmma::fragment<wmma::accumulator, 16, 16, 8, float> CFrag;

// ==========================================================================
// K1: fused QKV projection.
//   out[b,h,s,dk] = sum_d X[b,s,d] * W[h,d,dk]
// grid: (MROWS/128, 3*H).  blockIdx.y -> (proj, head). 256 threads, 8 warps.
// Block tile 128x64, K-chunk 32, warp tile 32x32 (2x2 fragments).
// ==========================================================================
__global__ __launch_bounds__(256) void proj_kernel(
    const float* __restrict__ Xq, const float* __restrict__ Xk, const float* __restrict__ Xv,
    const float* __restrict__ Wq, const float* __restrict__ Wk, const float* __restrict__ Wv)
{
    __shared__ float sA[128 * 32];
    __shared__ float sB[32 * 64];

    const int pz = blockIdx.y >> 4;       // 0:q 1:k 2:v
    const int h  = blockIdx.y & 15;
    const float* X = (pz == 0) ? Xq : (pz == 1) ? Xk : Xv;
    const float* W = ((pz == 0) ? Wq : (pz == 1) ? Wk : Wv) + (size_t)h * HID * D_;
    float* Out = (pz == 0) ? g_q : (pz == 1) ? g_k : g_v;

    const int m0   = blockIdx.x * 128;
    const int tid  = threadIdx.x;
    const int warp = tid >> 5;
    const int wm   = warp & 3;            // 4 row-strips of 32
    const int wn   = warp >> 2;           // 2 col-strips of 32

    CFrag acc[2][2];
#pragma unroll
    for (int i = 0; i < 2; i++)
#pragma unroll
        for (int j = 0; j < 2; j++) wmma::fill_fragment(acc[i][j], 0.0f);

    for (int k0 = 0; k0 < HID; k0 += 32) {
        for (int i = tid; i < 128 * 32; i += 256) {
            int r = i >> 5, c = i & 31;
            sA[i] = X[(size_t)(m0 + r) * HID + k0 + c];
        }
        for (int i = tid; i < 32 * 64; i += 256) {
            int r = i >> 6, c = i & 63;
            sB[i] = W[(size_t)(k0 + r) * D_ + c];
        }
        __syncthreads();

#pragma unroll
        for (int kk = 0; kk < 4; kk++) {
            AFrag ahi[2], alo[2];
#pragma unroll
            for (int i = 0; i < 2; i++) {
                AFrag araw;
                wmma::load_matrix_sync(araw, sA + (wm * 32 + i * 16) * 32 + kk * 8, 32);
                split_tf32(ahi[i], alo[i], araw);
            }
#pragma unroll
            for (int j = 0; j < 2; j++) {
                BFragR braw, bhi, blo;
                wmma::load_matrix_sync(braw, sB + (kk * 8) * 64 + wn * 32 + j * 16, 64);
                split_tf32(bhi, blo, braw);
#pragma unroll
                for (int i = 0; i < 2; i++) {
                    wmma::mma_sync(acc[i][j], ahi[i], bhi, acc[i][j]);
                    wmma::mma_sync(acc[i][j], ahi[i], blo, acc[i][j]);
                    wmma::mma_sync(acc[i][j], alo[i], bhi, acc[i][j]);
                }
            }
        }
        __syncthreads();
    }

    const int b  = m0 >> 11;              // S_=2048 rows per batch
    const int s0 = m0 & (S_ - 1);
    float* obase = Out + ((size_t)(b * H_ + h) * S_ + s0) * D_;
#pragma unroll
    for (int i = 0; i < 2; i++)
#pragma unroll
        for (int j = 0; j < 2; j++)
            wmma::store_matrix_sync(obase + (size_t)(wm * 32 + i * 16) * D_ + wn * 32 + j * 16,
                                    acc[i][j], D_, wmma::mem_row_major);
}

// ==========================================================================
// K2: attention.  grid (S/QB, B*H), 256 threads (8 warps).
// Per block: 64 query rows of one (b,h). Two passes over 16 KV chunks of 128:
//   pass1: S = Q K^T / 8 -> rowsum(exp)
//   pass2: recompute S, write attn = exp*inv_sum, accumulate O = P V,
//          store O into concat layout.
// Scores ~N(0,1): exp without max-subtraction is safe.
// ==========================================================================
__global__ __launch_bounds__(256) void attn_kernel(float* __restrict__ attn_out)
{
    extern __shared__ float sm[];
    float* sQ   = sm;                    // QB*D_   = 4096
    float* sK   = sQ + QB * D_;          // TB*D_   = 8192
    float* sV   = sK + TB * D_;          // TB*D_   = 8192
    float* sP   = sV + TB * D_;          // QB*TB   = 8192
    float* sSum = sP + QB * TB;          // QB

    const int bh  = blockIdx.y;
    const int qb  = blockIdx.x;
    const int tid = threadIdx.x;
    const int warp = tid >> 5;
    const int wm = warp & 3;             // S rows: wm*16 ; O rows: wm*16
    const int wn = warp >> 2;            // S cols: wn*64 ; O cols: wn*32

    const float* Qg = g_q + ((size_t)bh * S_ + (size_t)qb * QB) * D_;
    const float* Kg = g_k + (size_t)bh * S_ * D_;
    const float* Vg = g_v + (size_t)bh * S_ * D_;

    for (int i = tid; i < QB * D_; i += 256) sQ[i] = Qg[i];
    if (tid < QB) sSum[tid] = 0.0f;
    __syncthreads();

    // ---------------- pass 1: rowsum of exp(score/8) ----------------------
    for (int ch = 0; ch < NCH; ch++) {
        __syncthreads();
        const float* Kc = Kg + (size_t)ch * TB * D_;
        for (int i = tid; i < TB * D_; i += 256) sK[i] = Kc[i];
        __syncthreads();

        CFrag accS[4];
#pragma unroll
        for (int j = 0; j < 4; j++) wmma::fill_fragment(accS[j], 0.0f);

#pragma unroll
        for (int kk = 0; kk < 8; kk++) {
            AFrag araw, ahi, alo;
            wmma::load_matrix_sync(araw, sQ + (wm * 16) * D_ + kk * 8, D_);
            split_tf32(ahi, alo, araw);
#pragma unroll
            for (int j = 0; j < 4; j++) {
                BFragC braw, bhi, blo;
                wmma::load_matrix_sync(braw, sK + (wn * 64 + j * 16) * D_ + kk * 8, D_);
                split_tf32(bhi, blo, braw);
                wmma::mma_sync(accS[j], ahi, bhi, accS[j]);
                wmma::mma_sync(accS[j], ahi, blo, accS[j]);
                wmma::mma_sync(accS[j], alo, bhi, accS[j]);
            }
        }
#pragma unroll
        for (int j = 0; j < 4; j++)
            wmma::store_matrix_sync(sP + (wm * 16) * TB + wn * 64 + j * 16, accS[j],
                                    TB, wmma::mem_row_major);
        __syncthreads();

        {
            int r = tid >> 2, part = tid & 3;
            float acc = 0.0f;
#pragma unroll 8
            for (int c = part * 32; c < part * 32 + 32; c++)
                acc += __expf(sP[r * TB + c] * 0.125f);
            atomicAdd(&sSum[r], acc);
        }
    }
    __syncthreads();
    if (tid < QB) sSum[tid] = 1.0f / sSum[tid];
    __syncthreads();

    // ---------------- pass 2: attn write + O accumulation -----------------
    CFrag accO[2];
#pragma unroll
    for (int j = 0; j < 2; j++) wmma::fill_fragment(accO[j], 0.0f);

    for (int ch = 0; ch < NCH; ch++) {
        __syncthreads();
        const float* Kc = Kg + (size_t)ch * TB * D_;
        const float* Vc = Vg + (size_t)ch * TB * D_;
        for (int i = tid; i < TB * D_; i += 256) { sK[i] = Kc[i]; sV[i] = Vc[i]; }
        __syncthreads();

        CFrag accS[4];
#pragma unroll
        for (int j = 0; j < 4; j++) wmma::fill_fragment(accS[j], 0.0f);
#pragma unroll
        for (int kk = 0; kk < 8; kk++) {
            AFrag araw, ahi, alo;
            wmma::load_matrix_sync(araw, sQ + (wm * 16) * D_ + kk * 8, D_);
            split_tf32(ahi, alo, araw);
#pragma unroll
            for (int j = 0; j < 4; j++) {
                BFragC braw, bhi, blo;
                wmma::load_matrix_sync(braw, sK + (wn * 64 + j * 16) * D_ + kk * 8, D_);
                split_tf32(bhi, blo, braw);
                wmma::mma_sync(accS[j], ahi, bhi, accS[j]);
                wmma::mma_sync(accS[j], ahi, blo, accS[j]);
                wmma::mma_sync(accS[j], alo, bhi, accS[j]);
            }
        }
#pragma unroll
        for (int j = 0; j < 4; j++)
            wmma::store_matrix_sync(sP + (wm * 16) * TB + wn * 64 + j * 16, accS[j],
                                    TB, wmma::mem_row_major);
        __syncthreads();

        // normalize in smem + stream normalized attn to global
        {
            const size_t arow0 = (size_t)bh * S_ + (size_t)qb * QB;
            for (int i = tid; i < QB * TB; i += 256) {
                int r = i >> 7, c = i & 127;
                float e = __expf(sP[i] * 0.125f) * sSum[r];
                sP[i] = e;
                if (attn_out)
                    attn_out[(arow0 + r) * S_ + (size_t)ch * TB + c] = e;
            }
        }
        __syncthreads();

        // O += P * V   (P: [QB x TB], V: [TB x D_])
#pragma unroll
        for (int kk = 0; kk < 16; kk++) {
            AFrag araw, ahi, alo;
            wmma::load_matrix_sync(araw, sP + (wm * 16) * TB + kk * 8, TB);
            split_tf32(ahi, alo, araw);
#pragma unroll
            for (int j = 0; j < 2; j++) {
                BFragR braw, bhi, blo;
                wmma::load_matrix_sync(braw, sV + (kk * 8) * D_ + wn * 32 + j * 16, D_);
                split_tf32(bhi, blo, braw);
                wmma::mma_sync(accO[j], ahi, bhi, accO[j]);
                wmma::mma_sync(accO[j], ahi, blo, accO[j]);
                wmma::mma_sync(accO[j], alo, bhi, accO[j]);
            }
        }
    }

    // store O into concat layout [B, S, H*D]
    const int b = bh >> 4, h = bh & 15;
    float* obase = g_concat + ((size_t)b * S_ + (size_t)qb * QB + wm * 16) * HID + h * D_ + wn * 32;
#pragma unroll
    for (int j = 0; j < 2; j++)
        wmma::store_matrix_sync(obase + j * 16, accO[j], HID, wmma::mem_row_major);
}

// ==========================================================================
// K3: out = concat @ Wo.   M=4096, N=1024, K=1024.
// grid (32, 16), block tile 128x64, same warp layout as K1.
// ==========================================================================
__global__ __launch_bounds__(256) void outproj_kernel(
    const float* __restrict__ Wo, float* __restrict__ out)
{
    __shared__ float sA[128 * 32];
    __shared__ float sB[32 * 64];

    const int m0 = blockIdx.x * 128;
    const int n0 = blockIdx.y * 64;
    const int tid = threadIdx.x;
    const int warp = tid >> 5;
    const int wm = warp & 3;
    const int wn = warp >> 2;

    CFrag acc[2][2];
#pragma unroll
    for (int i = 0; i < 2; i++)
#pragma unroll
        for (int j = 0; j < 2; j++) wmma::fill_fragment(acc[i][j], 0.0f);

    for (int k0 = 0; k0 < HID; k0 += 32) {
        for (int i = tid; i < 128 * 32; i += 256) {
            int r = i >> 5, c = i & 31;
            sA[i] = g_concat[(size_t)(m0 + r) * HID + k0 + c];
        }
        for (int i = tid; i < 32 * 64; i += 256) {
            int r = i >> 6, c = i & 63;
            sB[i] = Wo[(size_t)(k0 + r) * HID + n0 + c];
        }
        __syncthreads();

#pragma unroll
        for (int kk = 0; kk < 4; kk++) {
            AFrag ahi[2], alo[2];
#pragma unroll
            for (int i = 0; i < 2; i++) {
                AFrag araw;
                wmma::load_matrix_sync(araw, sA + (wm * 32 + i * 16) * 32 + kk * 8, 32);
                split_tf32(ahi[i], alo[i], araw);
            }
#pragma unroll
            for (int j = 0; j < 2; j++) {
                BFragR braw, bhi, blo;
                wmma::load_matrix_sync(braw, sB + (kk * 8) * 64 + wn * 32 + j * 16, 64);
                split_tf32(bhi, blo, braw);
#pragma unroll
                for (int i = 0; i < 2; i++) {
                    wmma::mma_sync(acc[i][j], ahi[i], bhi, acc[i][j]);
                    wmma::mma_sync(acc[i][j], ahi[i], blo, acc[i][j]);
                    wmma::mma_sync(acc[i][j], alo[i], bhi, acc[i][j]);
                }
            }
        }
        __syncthreads();
    }

    float* obase = out + (size_t)(m0) * HID + n0;
#pragma unroll
    for (int i = 0; i < 2; i++)
#pragma unroll
        for (int j = 0; j < 2; j++)
            wmma::store_matrix_sync(obase + (size_t)(wm * 32 + i * 16) * HID + wn * 32 + j * 16,
                                    acc[i][j], HID, wmma::mem_row_major);
}

// ==========================================================================
extern "C" void kernel_launch(void* const* d_in, const int* in_sizes, int n_in,
                              void* d_out, int out_size)
{
    const float* q  = (const float*)d_in[0];
    const float* k  = (const float*)d_in[1];
    const float* v  = (const float*)d_in[2];
    const float* Wq = (const float*)d_in[3];
    const float* Wk = (const float*)d_in[4];
    const float* Wv = (const float*)d_in[5];
    const float* Wo = (const float*)d_in[6];

    float* out  = (float*)d_out;
    float* attn = nullptr;
    const long long OUT_ELEMS  = (long long)MROWS * HID;                 // 4,194,304
    const long long ATTN_ELEMS = (long long)B_ * H_ * S_ * S_;           // 134,217,728
    if ((long long)out_size >= OUT_ELEMS + ATTN_ELEMS)
        attn = out + OUT_ELEMS;

    const int attn_smem = (QB * D_ + 2 * TB * D_ + QB * TB + QB + 32) * (int)sizeof(float);
    cudaFuncSetAttribute(attn_kernel, cudaFuncAttributeMaxDynamicSharedMemorySize, attn_smem);

    dim3 g1(MROWS / 128, 3 * H_);
    proj_kernel<<<g1, 256>>>(q, k, v, Wq, Wk, Wv);

    dim3 g2(S_ / QB, B_ * H_);
    attn_kernel<<<g2, 256, attn_smem>>>(attn);

    dim3 g3(MROWS / 128, HID / 64);
    outproj_kernel<<<g3, 256>>>(Wo, out);
}

// round 3
// speedup vs baseline: 2.6364x; 2.6364x over previous
#include <cuda_runtime.h>
#include <cuda_bf16.h>
#include <mma.h>

using namespace nvcuda;

#define B_   2
#define S_   2048
#define H_   16
#define D_   64
#define HID  1024
#define MROWS (B_*S_)          // 4096

#define QB 64
#define TB 128
#define NCH (S_/TB)            // 16

// ---------------- scratch (static device memory; no allocations) ----------
__device__ float g_q[(size_t)B_*H_*S_*D_];
__device__ float g_k[(size_t)B_*H_*S_*D_];
__device__ float g_v[(size_t)B_*H_*S_*D_];
__device__ float g_concat[(size_t)MROWS*HID];

// ---------------- fragment types ------------------------------------------
typedef wmma::fragment<wmma::matrix_a, 16, 16, 16, __nv_bfloat16, wmma::row_major> ABf;
typedef wmma::fragment<wmma::matrix_b, 16, 16, 16, __nv_bfloat16, wmma::row_major> BBfR;
typedef wmma::fragment<wmma::matrix_b, 16, 16, 16, __nv_bfloat16, wmma::col_major> BBfC;
typedef wmma::fragment<wmma::accumulator, 16, 16, 16, float> CBf;

typedef wmma::fragment<wmma::matrix_a, 16, 16, 8, wmma::precision::tf32, wmma::row_major> ATf;
typedef wmma::fragment<wmma::matrix_b, 16, 16, 8, wmma::precision::tf32, wmma::col_major> BTfC;
typedef wmma::fragment<wmma::accumulator, 16, 16, 8, float> CTf;

__device__ __forceinline__ void split_store(float x, __nv_bfloat16* hi, __nv_bfloat16* lo) {
    __nv_bfloat16 h = __float2bfloat16(x);
    *hi = h;
    *lo = __float2bfloat16(x - __bfloat162float(h));
}

// pad: bf16 rows +8, f32 rows +4
#define LDB16 72
#define LDF32 68
#define LDP   132   // f32 P tile (cols 128)
#define LDPB  136   // bf16 P tile

// ==========================================================================
// K1: fused QKV projection (bf16-split-3).
// grid: (32, 48). block 256 (8 warps). Block tile 128x64, K-chunk 64.
// ==========================================================================
__global__ __launch_bounds__(256) void proj_kernel(
    const float* __restrict__ Xq, const float* __restrict__ Xk, const float* __restrict__ Xv,
    const float* __restrict__ Wq, const float* __restrict__ Wk, const float* __restrict__ Wv)
{
    extern __shared__ char smraw[];
    __nv_bfloat16* sAhi = (__nv_bfloat16*)smraw;                 // 128*72
    __nv_bfloat16* sAlo = sAhi + 128 * LDB16;
    __nv_bfloat16* sBhi = sAlo + 128 * LDB16;                    // 64*72
    __nv_bfloat16* sBlo = sBhi + 64 * LDB16;

    const int pz = blockIdx.y >> 4;
    const int h  = blockIdx.y & 15;
    const float* X = (pz == 0) ? Xq : (pz == 1) ? Xk : Xv;
    const float* W = ((pz == 0) ? Wq : (pz == 1) ? Wk : Wv) + (size_t)h * HID * D_;
    float* Out = (pz == 0) ? g_q : (pz == 1) ? g_k : g_v;

    const int m0   = blockIdx.x * 128;
    const int tid  = threadIdx.x;
    const int warp = tid >> 5;
    const int wm   = warp & 3;
    const int wn   = warp >> 2;

    CBf acc[2][2];
#pragma unroll
    for (int i = 0; i < 2; i++)
#pragma unroll
        for (int j = 0; j < 2; j++) wmma::fill_fragment(acc[i][j], 0.0f);

    for (int k0 = 0; k0 < HID; k0 += 64) {
        // A tile 128x64 (float2 vectorized)
#pragma unroll
        for (int i = tid; i < 128 * 32; i += 256) {
            int r = i >> 5, c2 = (i & 31) * 2;
            float2 v = *(const float2*)&X[(size_t)(m0 + r) * HID + k0 + c2];
            split_store(v.x, &sAhi[r * LDB16 + c2],     &sAlo[r * LDB16 + c2]);
            split_store(v.y, &sAhi[r * LDB16 + c2 + 1], &sAlo[r * LDB16 + c2 + 1]);
        }
        // B tile 64x64
#pragma unroll
        for (int i = tid; i < 64 * 32; i += 256) {
            int r = i >> 5, c2 = (i & 31) * 2;
            float2 v = *(const float2*)&W[(size_t)(k0 + r) * D_ + c2];
            split_store(v.x, &sBhi[r * LDB16 + c2],     &sBlo[r * LDB16 + c2]);
            split_store(v.y, &sBhi[r * LDB16 + c2 + 1], &sBlo[r * LDB16 + c2 + 1]);
        }
        __syncthreads();

#pragma unroll
        for (int kk = 0; kk < 4; kk++) {
            ABf ahi[2], alo[2];
#pragma unroll
            for (int i = 0; i < 2; i++) {
                wmma::load_matrix_sync(ahi[i], sAhi + (wm * 32 + i * 16) * LDB16 + kk * 16, LDB16);
                wmma::load_matrix_sync(alo[i], sAlo + (wm * 32 + i * 16) * LDB16 + kk * 16, LDB16);
            }
#pragma unroll
            for (int j = 0; j < 2; j++) {
                BBfR bhi, blo;
                wmma::load_matrix_sync(bhi, sBhi + (kk * 16) * LDB16 + wn * 32 + j * 16, LDB16);
                wmma::load_matrix_sync(blo, sBlo + (kk * 16) * LDB16 + wn * 32 + j * 16, LDB16);
#pragma unroll
                for (int i = 0; i < 2; i++) {
                    wmma::mma_sync(acc[i][j], ahi[i], bhi, acc[i][j]);
                    wmma::mma_sync(acc[i][j], ahi[i], blo, acc[i][j]);
                    wmma::mma_sync(acc[i][j], alo[i], bhi, acc[i][j]);
                }
            }
        }
        __syncthreads();
    }

    const int b  = m0 >> 11;
    const int s0 = m0 & (S_ - 1);
    float* obase = Out + ((size_t)(b * H_ + h) * S_ + s0) * D_;
#pragma unroll
    for (int i = 0; i < 2; i++)
#pragma unroll
        for (int j = 0; j < 2; j++)
            wmma::store_matrix_sync(obase + (size_t)(wm * 32 + i * 16) * D_ + wn * 32 + j * 16,
                                    acc[i][j], D_, wmma::mem_row_major);
}

// ==========================================================================
// K2: attention. grid (32, 32), 256 threads.
// pass1: single-tf32 S -> rowsum(exp)  (sum only needs ~1e-4 accuracy)
// pass2: bf16-split S -> normalized attn write + O = P V (bf16-split)
// ==========================================================================

// dynamic smem layout (bytes)
#define SQF_OFF   0                       // f32 [64][68]  = 17408
#define SQHI_OFF  17408                   // bf16 [64][72] =  9216
#define SQLO_OFF  26624
#define SSUM_OFF  35840                   // f32 [64]
#define SP_OFF    36096                   // f32 [64][132] = 33792
#define CHUNK_OFF 69888
//   pass1: sKf  f32 [128][68] = 34816
//   pass2: sKhi/sKlo/sVhi/sVlo bf16 [128][72] = 18432 each (73728)
//          sPhi/sPlo bf16 [64][136] = 17408 each  (34816)
#define ATTN_SMEM (CHUNK_OFF + 108544)    // 178432 bytes

__global__ __launch_bounds__(256) void attn_kernel(float* __restrict__ attn_out)
{
    extern __shared__ char smraw[];
    float*         sQf  = (float*)(smraw + SQF_OFF);
    __nv_bfloat16* sQhi = (__nv_bfloat16*)(smraw + SQHI_OFF);
    __nv_bfloat16* sQlo = (__nv_bfloat16*)(smraw + SQLO_OFF);
    float*         sSum = (float*)(smraw + SSUM_OFF);
    float*         sP   = (float*)(smraw + SP_OFF);
    float*         sKf  = (float*)(smraw + CHUNK_OFF);
    __nv_bfloat16* sKhi = (__nv_bfloat16*)(smraw + CHUNK_OFF);
    __nv_bfloat16* sKlo = sKhi + 128 * LDB16;
    __nv_bfloat16* sVhi = sKlo + 128 * LDB16;
    __nv_bfloat16* sVlo = sVhi + 128 * LDB16;
    __nv_bfloat16* sPhi = sVlo + 128 * LDB16;
    __nv_bfloat16* sPlo = sPhi + 64 * LDPB;

    const int bh  = blockIdx.y;
    const int qb  = blockIdx.x;
    const int tid = threadIdx.x;
    const int warp = tid >> 5;
    const int wm = warp & 3;             // 4 row strips of 16
    const int wn = warp >> 2;            // 2 col strips (S: 64, O: 32)

    const float* Qg = g_q + ((size_t)bh * S_ + (size_t)qb * QB) * D_;
    const float* Kg = g_k + (size_t)bh * S_ * D_;
    const float* Vg = g_v + (size_t)bh * S_ * D_;

    // load Q: f32 copy (pass1) + bf16 split (pass2)
#pragma unroll
    for (int i = tid; i < QB * 32; i += 256) {
        int r = i >> 5, c2 = (i & 31) * 2;
        float2 v = *(const float2*)&Qg[(size_t)r * D_ + c2];
        sQf[r * LDF32 + c2]     = v.x;
        sQf[r * LDF32 + c2 + 1] = v.y;
        split_store(v.x, &sQhi[r * LDB16 + c2],     &sQlo[r * LDB16 + c2]);
        split_store(v.y, &sQhi[r * LDB16 + c2 + 1], &sQlo[r * LDB16 + c2 + 1]);
    }
    if (tid < QB) sSum[tid] = 0.0f;
    __syncthreads();

    // ---------------- pass 1: rowsum of exp(score/8), single tf32 ---------
    for (int ch = 0; ch < NCH; ch++) {
        __syncthreads();
        const float* Kc = Kg + (size_t)ch * TB * D_;
#pragma unroll
        for (int i = tid; i < TB * 32; i += 256) {
            int r = i >> 5, c2 = (i & 31) * 2;
            float2 v = *(const float2*)&Kc[(size_t)r * D_ + c2];
            sKf[r * LDF32 + c2]     = v.x;
            sKf[r * LDF32 + c2 + 1] = v.y;
        }
        __syncthreads();

        CTf accS[4];
#pragma unroll
        for (int j = 0; j < 4; j++) wmma::fill_fragment(accS[j], 0.0f);
#pragma unroll
        for (int kk = 0; kk < 8; kk++) {
            ATf a;
            wmma::load_matrix_sync(a, sQf + (wm * 16) * LDF32 + kk * 8, LDF32);
#pragma unroll
            for (int e = 0; e < a.num_elements; e++) a.x[e] = wmma::__float_to_tf32(a.x[e]);
#pragma unroll
            for (int j = 0; j < 4; j++) {
                BTfC b;
                wmma::load_matrix_sync(b, sKf + (wn * 64 + j * 16) * LDF32 + kk * 8, LDF32);
#pragma unroll
                for (int e = 0; e < b.num_elements; e++) b.x[e] = wmma::__float_to_tf32(b.x[e]);
                wmma::mma_sync(accS[j], a, b, accS[j]);
            }
        }
#pragma unroll
        for (int j = 0; j < 4; j++)
            wmma::store_matrix_sync(sP + (wm * 16) * LDP + wn * 64 + j * 16, accS[j],
                                    LDP, wmma::mem_row_major);
        __syncthreads();

        {
            int r = tid >> 2, part = tid & 3;
            float acc = 0.0f;
#pragma unroll 8
            for (int c = part * 32; c < part * 32 + 32; c++)
                acc += __expf(sP[r * LDP + c] * 0.125f);
            atomicAdd(&sSum[r], acc);
        }
    }
    __syncthreads();
    if (tid < QB) sSum[tid] = 1.0f / sSum[tid];
    __syncthreads();

    // ---------------- pass 2: attn write + O accumulation (bf16-split) ----
    CBf accO[2];
#pragma unroll
    for (int j = 0; j < 2; j++) wmma::fill_fragment(accO[j], 0.0f);

    for (int ch = 0; ch < NCH; ch++) {
        __syncthreads();
        const float* Kc = Kg + (size_t)ch * TB * D_;
        const float* Vc = Vg + (size_t)ch * TB * D_;
#pragma unroll
        for (int i = tid; i < TB * 32; i += 256) {
            int r = i >> 5, c2 = (i & 31) * 2;
            float2 vk = *(const float2*)&Kc[(size_t)r * D_ + c2];
            float2 vv = *(const float2*)&Vc[(size_t)r * D_ + c2];
            split_store(vk.x, &sKhi[r * LDB16 + c2],     &sKlo[r * LDB16 + c2]);
            split_store(vk.y, &sKhi[r * LDB16 + c2 + 1], &sKlo[r * LDB16 + c2 + 1]);
            split_store(vv.x, &sVhi[r * LDB16 + c2],     &sVlo[r * LDB16 + c2]);
            split_store(vv.y, &sVhi[r * LDB16 + c2 + 1], &sVlo[r * LDB16 + c2 + 1]);
        }
        __syncthreads();

        CBf accS[4];
#pragma unroll
        for (int j = 0; j < 4; j++) wmma::fill_fragment(accS[j], 0.0f);
#pragma unroll
        for (int kk = 0; kk < 4; kk++) {
            ABf ahi, alo;
            wmma::load_matrix_sync(ahi, sQhi + (wm * 16) * LDB16 + kk * 16, LDB16);
            wmma::load_matrix_sync(alo, sQlo + (wm * 16) * LDB16 + kk * 16, LDB16);
#pragma unroll
            for (int j = 0; j < 4; j++) {
                BBfC bhi, blo;
                wmma::load_matrix_sync(bhi, sKhi + (wn * 64 + j * 16) * LDB16 + kk * 16, LDB16);
                wmma::load_matrix_sync(blo, sKlo + (wn * 64 + j * 16) * LDB16 + kk * 16, LDB16);
                wmma::mma_sync(accS[j], ahi, bhi, accS[j]);
                wmma::mma_sync(accS[j], ahi, blo, accS[j]);
                wmma::mma_sync(accS[j], alo, bhi, accS[j]);
            }
        }
#pragma unroll
        for (int j = 0; j < 4; j++)
            wmma::store_matrix_sync(sP + (wm * 16) * LDP + wn * 64 + j * 16, accS[j],
                                    LDP, wmma::mem_row_major);
        __syncthreads();

        // normalize + exp, write attn, convert P to bf16 split
        {
            const size_t arow0 = (size_t)bh * S_ + (size_t)qb * QB;
#pragma unroll
            for (int i = tid; i < QB * 64; i += 256) {
                int r = i >> 6, c2 = (i & 63) * 2;
                float inv = sSum[r];
                float e0 = __expf(sP[r * LDP + c2]     * 0.125f) * inv;
                float e1 = __expf(sP[r * LDP + c2 + 1] * 0.125f) * inv;
                if (attn_out) {
                    float2 w = make_float2(e0, e1);
                    *(float2*)&attn_out[(arow0 + r) * S_ + (size_t)ch * TB + c2] = w;
                }
                split_store(e0, &sPhi[r * LDPB + c2],     &sPlo[r * LDPB + c2]);
                split_store(e1, &sPhi[r * LDPB + c2 + 1], &sPlo[r * LDPB + c2 + 1]);
            }
        }
        __syncthreads();

        // O += P * V
#pragma unroll
        for (int kk = 0; kk < 8; kk++) {
            ABf ahi, alo;
            wmma::load_matrix_sync(ahi, sPhi + (wm * 16) * LDPB + kk * 16, LDPB);
            wmma::load_matrix_sync(alo, sPlo + (wm * 16) * LDPB + kk * 16, LDPB);
#pragma unroll
            for (int j = 0; j < 2; j++) {
                BBfR bhi, blo;
                wmma::load_matrix_sync(bhi, sVhi + (kk * 16) * LDB16 + wn * 32 + j * 16, LDB16);
                wmma::load_matrix_sync(blo, sVlo + (kk * 16) * LDB16 + wn * 32 + j * 16, LDB16);
                wmma::mma_sync(accO[j], ahi, bhi, accO[j]);
                wmma::mma_sync(accO[j], ahi, blo, accO[j]);
                wmma::mma_sync(accO[j], alo, bhi, accO[j]);
            }
        }
    }

    const int b = bh >> 4, h = bh & 15;
    float* obase = g_concat + ((size_t)b * S_ + (size_t)qb * QB + wm * 16) * HID + h * D_ + wn * 32;
#pragma unroll
    for (int j = 0; j < 2; j++)
        wmma::store_matrix_sync(obase + j * 16, accO[j], HID, wmma::mem_row_major);
}

// ==========================================================================
// K3: out = concat @ Wo  (bf16-split-3). grid (32, 16).
// ==========================================================================
__global__ __launch_bounds__(256) void outproj_kernel(
    const float* __restrict__ Wo, float* __restrict__ out)
{
    extern __shared__ char smraw[];
    __nv_bfloat16* sAhi = (__nv_bfloat16*)smraw;
    __nv_bfloat16* sAlo = sAhi + 128 * LDB16;
    __nv_bfloat16* sBhi = sAlo + 128 * LDB16;
    __nv_bfloat16* sBlo = sBhi + 64 * LDB16;

    const int m0 = blockIdx.x * 128;
    const int n0 = blockIdx.y * 64;
    const int tid = threadIdx.x;
    const int warp = tid >> 5;
    const int wm = warp & 3;
    const int wn = warp >> 2;

    CBf acc[2][2];
#pragma unroll
    for (int i = 0; i < 2; i++)
#pragma unroll
        for (int j = 0; j < 2; j++) wmma::fill_fragment(acc[i][j], 0.0f);

    for (int k0 = 0; k0 < HID; k0 += 64) {
#pragma unroll
        for (int i = tid; i < 128 * 32; i += 256) {
            int r = i >> 5, c2 = (i & 31) * 2;
            float2 v = *(const float2*)&g_concat[(size_t)(m0 + r) * HID + k0 + c2];
            split_store(v.x, &sAhi[r * LDB16 + c2],     &sAlo[r * LDB16 + c2]);
            split_store(v.y, &sAhi[r * LDB16 + c2 + 1], &sAlo[r * LDB16 + c2 + 1]);
        }
#pragma unroll
        for (int i = tid; i < 64 * 32; i += 256) {
            int r = i >> 5, c2 = (i & 31) * 2;
            float2 v = *(const float2*)&Wo[(size_t)(k0 + r) * HID + n0 + c2];
            split_store(v.x, &sBhi[r * LDB16 + c2],     &sBlo[r * LDB16 + c2]);
            split_store(v.y, &sBhi[r * LDB16 + c2 + 1], &sBlo[r * LDB16 + c2 + 1]);
        }
        __syncthreads();

#pragma unroll
        for (int kk = 0; kk < 4; kk++) {
            ABf ahi[2], alo[2];
#pragma unroll
            for (int i = 0; i < 2; i++) {
                wmma::load_matrix_sync(ahi[i], sAhi + (wm * 32 + i * 16) * LDB16 + kk * 16, LDB16);
                wmma::load_matrix_sync(alo[i], sAlo + (wm * 32 + i * 16) * LDB16 + kk * 16, LDB16);
            }
#pragma unroll
            for (int j = 0; j < 2; j++) {
                BBfR bhi, blo;
                wmma::load_matrix_sync(bhi, sBhi + (kk * 16) * LDB16 + wn * 32 + j * 16, LDB16);
                wmma::load_matrix_sync(blo, sBlo + (kk * 16) * LDB16 + wn * 32 + j * 16, LDB16);
#pragma unroll
                for (int i = 0; i < 2; i++) {
                    wmma::mma_sync(acc[i][j], ahi[i], bhi, acc[i][j]);
                    wmma::mma_sync(acc[i][j], ahi[i], blo, acc[i][j]);
                    wmma::mma_sync(acc[i][j], alo[i], bhi, acc[i][j]);
                }
            }
        }
        __syncthreads();
    }

    float* obase = out + (size_t)m0 * HID + n0;
#pragma unroll
    for (int i = 0; i < 2; i++)
#pragma unroll
        for (int j = 0; j < 2; j++)
            wmma::store_matrix_sync(obase + (size_t)(wm * 32 + i * 16) * HID + wn * 32 + j * 16,
                                    acc[i][j], HID, wmma::mem_row_major);
}

// ==========================================================================
extern "C" void kernel_launch(void* const* d_in, const int* in_sizes, int n_in,
                              void* d_out, int out_size)
{
    const float* q  = (const float*)d_in[0];
    const float* k  = (const float*)d_in[1];
    const float* v  = (const float*)d_in[2];
    const float* Wq = (const float*)d_in[3];
    const float* Wk = (const float*)d_in[4];
    const float* Wv = (const float*)d_in[5];
    const float* Wo = (const float*)d_in[6];

    float* out  = (float*)d_out;
    float* attn = nullptr;
    const long long OUT_ELEMS  = (long long)MROWS * HID;
    const long long ATTN_ELEMS = (long long)B_ * H_ * S_ * S_;
    if ((long long)out_size >= OUT_ELEMS + ATTN_ELEMS)
        attn = out + OUT_ELEMS;

    const int proj_smem = (128 + 64) * LDB16 * 2 * 2;   // 55296 bytes
    cudaFuncSetAttribute(proj_kernel,    cudaFuncAttributeMaxDynamicSharedMemorySize, proj_smem);
    cudaFuncSetAttribute(outproj_kernel, cudaFuncAttributeMaxDynamicSharedMemorySize, proj_smem);
    cudaFuncSetAttribute(attn_kernel,    cudaFuncAttributeMaxDynamicSharedMemorySize, ATTN_SMEM);

    dim3 g1(MROWS / 128, 3 * H_);
    proj_kernel<<<g1, 256, proj_smem>>>(q, k, v, Wq, Wk, Wv);

    dim3 g2(S_ / QB, B_ * H_);
    attn_kernel<<<g2, 256, ATTN_SMEM>>>(attn);

    dim3 g3(MROWS / 128, HID / 64);
    outproj_kernel<<<g3, 256, proj_smem>>>(Wo, out);
}

// round 5
// speedup vs baseline: 2.9169x; 1.1064x over previous
#include <cuda_runtime.h>
#include <cuda_bf16.h>
#include <mma.h>

using namespace nvcuda;

#define B_   2
#define S_   2048
#define H_   16
#define D_   64
#define HID  1024
#define MROWS (B_*S_)          // 4096
#define QB 64
#define TB 128
#define NCH (S_/TB)            // 16
#define XN (MROWS*HID)         // 4,194,304
#define WN (H_*HID*D_)         // 1,048,576

// ---------------- global scratch (static; no allocations) -----------------
__device__ __nv_bfloat16 iq_hi[XN], iq_lo[XN], ik_hi[XN], ik_lo[XN], iv_hi[XN], iv_lo[XN];
__device__ __nv_bfloat16 wq_hi[WN], wq_lo[WN], wk_hi[WN], wk_lo[WN], wv_hi[WN], wv_lo[WN];
__device__ __nv_bfloat16 wo_hi[WN], wo_lo[WN];
__device__ __nv_bfloat16 pq_hi[XN], pq_lo[XN], pk_hi[XN], pk_lo[XN], pv_hi[XN], pv_lo[XN];
__device__ __nv_bfloat16 cat_hi[XN], cat_lo[XN];
__device__ float g_invsum[(size_t)B_*H_*S_];

// ---------------- fragment types ------------------------------------------
typedef wmma::fragment<wmma::matrix_a, 16, 16, 16, __nv_bfloat16, wmma::row_major> ABf;
typedef wmma::fragment<wmma::matrix_b, 16, 16, 16, __nv_bfloat16, wmma::row_major> BBfR;
typedef wmma::fragment<wmma::matrix_b, 16, 16, 16, __nv_bfloat16, wmma::col_major> BBfC;
typedef wmma::fragment<wmma::accumulator, 16, 16, 16, float> CBf;

__device__ __forceinline__ void split2(float x, __nv_bfloat16& hi, __nv_bfloat16& lo) {
    hi = __float2bfloat16(x);
    lo = __float2bfloat16(x - __bfloat162float(hi));
}

#define LDB16 72   // bf16 tile stride (64 + 8)
#define LDF32 68   // f32 staging stride
#define LDP   132  // f32 P tile stride (128 + 4)
#define LDPB  136  // bf16 P tile stride (128 + 8)

// ==========================================================================
// K0: presplit all f32 operands to bf16 hi/lo.
// 4096 blocks x 256 threads x 4 float4 each (1024 float4 = 4096 floats/blk).
// segments: q,k,v (1024 blocks each), Wq,Wk,Wv,Wo (256 each).
// ==========================================================================
__global__ __launch_bounds__(256) void presplit_kernel(
    const float* __restrict__ q, const float* __restrict__ k, const float* __restrict__ v,
    const float* __restrict__ Wq, const float* __restrict__ Wk, const float* __restrict__ Wv,
    const float* __restrict__ Wo)
{
    int blk = blockIdx.x;
    const float* src; __nv_bfloat16 *hi, *lo; int base;
    if      (blk < 1024) { src = q;  hi = iq_hi; lo = iq_lo; base = blk; }
    else if (blk < 2048) { src = k;  hi = ik_hi; lo = ik_lo; base = blk - 1024; }
    else if (blk < 3072) { src = v;  hi = iv_hi; lo = iv_lo; base = blk - 2048; }
    else if (blk < 3328) { src = Wq; hi = wq_hi; lo = wq_lo; base = blk - 3072; }
    else if (blk < 3584) { src = Wk; hi = wk_hi; lo = wk_lo; base = blk - 3328; }
    else if (blk < 3840) { src = Wv; hi = wv_hi; lo = wv_lo; base = blk - 3584; }
    else                 { src = Wo; hi = wo_hi; lo = wo_lo; base = blk - 3840; }

#pragma unroll
    for (int j = 0; j < 4; j++) {
        size_t i4 = (size_t)base * 1024 + j * 256 + threadIdx.x;   // float4 index
        float4 val = ((const float4*)src)[i4];
        __nv_bfloat16 h0,h1,h2,h3,l0,l1,l2,l3;
        split2(val.x, h0, l0); split2(val.y, h1, l1);
        split2(val.z, h2, l2); split2(val.w, h3, l3);
        ((__nv_bfloat162*)hi)[i4*2]   = __halves2bfloat162(h0, h1);
        ((__nv_bfloat162*)hi)[i4*2+1] = __halves2bfloat162(h2, h3);
        ((__nv_bfloat162*)lo)[i4*2]   = __halves2bfloat162(l0, l1);
        ((__nv_bfloat162*)lo)[i4*2+1] = __halves2bfloat162(l2, l3);
    }
}

// ==========================================================================
// K1: fused QKV projection. grid (32, 48), 256 threads, 2 blocks/SM.
// Operands pre-split bf16 in global; output written as bf16 hi/lo.
// ==========================================================================
__global__ __launch_bounds__(256, 2) void proj_kernel()
{
    extern __shared__ char smraw[];
    __nv_bfloat16* sAhi = (__nv_bfloat16*)smraw;             // 128*72
    __nv_bfloat16* sAlo = sAhi + 128 * LDB16;
    __nv_bfloat16* sBhi = sAlo + 128 * LDB16;                // 64*72
    __nv_bfloat16* sBlo = sBhi + 64 * LDB16;

    const int pz = blockIdx.y >> 4;
    const int h  = blockIdx.y & 15;
    const __nv_bfloat16* Xhi = (pz == 0) ? iq_hi : (pz == 1) ? ik_hi : iv_hi;
    const __nv_bfloat16* Xlo = (pz == 0) ? iq_lo : (pz == 1) ? ik_lo : iv_lo;
    const __nv_bfloat16* Whi = ((pz == 0) ? wq_hi : (pz == 1) ? wk_hi : wv_hi) + (size_t)h * HID * D_;
    const __nv_bfloat16* Wlo = ((pz == 0) ? wq_lo : (pz == 1) ? wk_lo : wv_lo) + (size_t)h * HID * D_;
    __nv_bfloat16* Ohi = (pz == 0) ? pq_hi : (pz == 1) ? pk_hi : pv_hi;
    __nv_bfloat16* Olo = (pz == 0) ? pq_lo : (pz == 1) ? pk_lo : pv_lo;

    const int m0   = blockIdx.x * 128;
    const int tid  = threadIdx.x;
    const int warp = tid >> 5;
    const int wm   = warp & 3;
    const int wn   = warp >> 2;

    CBf acc[2][2];
#pragma unroll
    for (int i = 0; i < 2; i++)
#pragma unroll
        for (int j = 0; j < 2; j++) wmma::fill_fragment(acc[i][j], 0.0f);

    for (int k0 = 0; k0 < HID; k0 += 64) {
        // A tile: 128x64 bf16 (hi+lo) = 1024 uint4 each
#pragma unroll
        for (int i = tid; i < 1024; i += 256) {
            int r = i >> 3, c8 = (i & 7) * 8;
            size_t g = (size_t)(m0 + r) * HID + k0 + c8;
            *(uint4*)&sAhi[r * LDB16 + c8] = *(const uint4*)&Xhi[g];
            *(uint4*)&sAlo[r * LDB16 + c8] = *(const uint4*)&Xlo[g];
        }
        // B tile: 64x64
#pragma unroll
        for (int i = tid; i < 512; i += 256) {
            int r = i >> 3, c8 = (i & 7) * 8;
            size_t g = (size_t)(k0 + r) * D_ + c8;
            *(uint4*)&sBhi[r * LDB16 + c8] = *(const uint4*)&Whi[g];
            *(uint4*)&sBlo[r * LDB16 + c8] = *(const uint4*)&Wlo[g];
        }
        __syncthreads();

#pragma unroll
        for (int kk = 0; kk < 4; kk++) {
            ABf ahi[2], alo[2];
#pragma unroll
            for (int i = 0; i < 2; i++) {
                wmma::load_matrix_sync(ahi[i], sAhi + (wm * 32 + i * 16) * LDB16 + kk * 16, LDB16);
                wmma::load_matrix_sync(alo[i], sAlo + (wm * 32 + i * 16) * LDB16 + kk * 16, LDB16);
            }
#pragma unroll
            for (int j = 0; j < 2; j++) {
                BBfR bhi, blo;
                wmma::load_matrix_sync(bhi, sBhi + (kk * 16) * LDB16 + wn * 32 + j * 16, LDB16);
                wmma::load_matrix_sync(blo, sBlo + (kk * 16) * LDB16 + wn * 32 + j * 16, LDB16);
#pragma unroll
                for (int i = 0; i < 2; i++) {
                    wmma::mma_sync(acc[i][j], ahi[i], bhi, acc[i][j]);
                    wmma::mma_sync(acc[i][j], ahi[i], blo, acc[i][j]);
                    wmma::mma_sync(acc[i][j], alo[i], bhi, acc[i][j]);
                }
            }
        }
        __syncthreads();
    }

    // stage f32 result in smem, then split-write to global bf16 hi/lo
    float* stage = (float*)smraw;                            // 128*68*4 = 34816 B
#pragma unroll
    for (int i = 0; i < 2; i++)
#pragma unroll
        for (int j = 0; j < 2; j++)
            wmma::store_matrix_sync(stage + (size_t)(wm * 32 + i * 16) * LDF32 + wn * 32 + j * 16,
                                    acc[i][j], LDF32, wmma::mem_row_major);
    __syncthreads();

    const int b  = m0 >> 11;
    const int s0 = m0 & (S_ - 1);
    const size_t orow0 = ((size_t)(b * H_ + h) * S_ + s0);
#pragma unroll
    for (int i = tid; i < 128 * 32; i += 256) {
        int r = i >> 5, c2 = (i & 31) * 2;
        float v0 = stage[r * LDF32 + c2], v1 = stage[r * LDF32 + c2 + 1];
        __nv_bfloat16 h0,h1,l0,l1;
        split2(v0, h0, l0); split2(v1, h1, l1);
        size_t g = (orow0 + r) * D_ + c2;
        *(__nv_bfloat162*)&Ohi[g] = __halves2bfloat162(h0, h1);
        *(__nv_bfloat162*)&Olo[g] = __halves2bfloat162(l0, l1);
    }
}

// ==========================================================================
// K2: one-pass attention. grid (32, 32), 256 threads.
// Per chunk: S=QK^T (3-term bf16) -> exp in-fragment -> write UNNORMALIZED
// attn, accumulate rowsum, split P -> O += P V (3-term).
// End: O *= 1/sum -> cat hi/lo; 1/sum -> g_invsum.
// ==========================================================================
#define ATTN_SMEM 161280

__global__ __launch_bounds__(256) void attn_kernel(float* __restrict__ attn_out)
{
    extern __shared__ char smraw[];
    __nv_bfloat16* sQhi = (__nv_bfloat16*)smraw;             // [64][72]
    __nv_bfloat16* sQlo = sQhi + QB * LDB16;
    __nv_bfloat16* sKhi = sQlo + QB * LDB16;                 // [128][72]
    __nv_bfloat16* sKlo = sKhi + TB * LDB16;
    __nv_bfloat16* sVhi = sKlo + TB * LDB16;
    __nv_bfloat16* sVlo = sVhi + TB * LDB16;
    __nv_bfloat16* sPhi = sVlo + TB * LDB16;                 // [64][136]
    __nv_bfloat16* sPlo = sPhi + QB * LDPB;
    float*         sP   = (float*)(sPlo + QB * LDPB);        // [64][132]
    float*         sSum = sP + QB * LDP;                     // [64]

    const int bh  = blockIdx.y;
    const int qb  = blockIdx.x;
    const int tid = threadIdx.x;
    const int warp = tid >> 5;
    const int wm = warp & 3;
    const int wn = warp >> 2;

    const size_t qrow0 = (size_t)bh * S_ + (size_t)qb * QB;
    const size_t krow0 = (size_t)bh * S_;

    // load Q tile (64x64 bf16 x2)
#pragma unroll
    for (int i = tid; i < 512; i += 256) {
        int r = i >> 3, c8 = (i & 7) * 8;
        size_t g = (qrow0 + r) * D_ + c8;
        *(uint4*)&sQhi[r * LDB16 + c8] = *(const uint4*)&pq_hi[g];
        *(uint4*)&sQlo[r * LDB16 + c8] = *(const uint4*)&pq_lo[g];
    }
    if (tid < QB) sSum[tid] = 0.0f;

    CBf accO[2];
#pragma unroll
    for (int j = 0; j < 2; j++) wmma::fill_fragment(accO[j], 0.0f);

    for (int ch = 0; ch < NCH; ch++) {
        __syncthreads();
        // load K/V chunk (128x64 bf16 x4 arrays)
#pragma unroll
        for (int i = tid; i < 1024; i += 256) {
            int r = i >> 3, c8 = (i & 7) * 8;
            size_t g = (krow0 + (size_t)ch * TB + r) * D_ + c8;
            *(uint4*)&sKhi[r * LDB16 + c8] = *(const uint4*)&pk_hi[g];
            *(uint4*)&sKlo[r * LDB16 + c8] = *(const uint4*)&pk_lo[g];
            *(uint4*)&sVhi[r * LDB16 + c8] = *(const uint4*)&pv_hi[g];
            *(uint4*)&sVlo[r * LDB16 + c8] = *(const uint4*)&pv_lo[g];
        }
        __syncthreads();

        // S = Q K^T (3-term split)
        CBf accS[4];
#pragma unroll
        for (int j = 0; j < 4; j++) wmma::fill_fragment(accS[j], 0.0f);
#pragma unroll
        for (int kk = 0; kk < 4; kk++) {
            ABf ahi, alo;
            wmma::load_matrix_sync(ahi, sQhi + (wm * 16) * LDB16 + kk * 16, LDB16);
            wmma::load_matrix_sync(alo, sQlo + (wm * 16) * LDB16 + kk * 16, LDB16);
#pragma unroll
            for (int j = 0; j < 4; j++) {
                BBfC bhi, blo;
                wmma::load_matrix_sync(bhi, sKhi + (wn * 64 + j * 16) * LDB16 + kk * 16, LDB16);
                wmma::load_matrix_sync(blo, sKlo + (wn * 64 + j * 16) * LDB16 + kk * 16, LDB16);
                wmma::mma_sync(accS[j], ahi, bhi, accS[j]);
                wmma::mma_sync(accS[j], ahi, blo, accS[j]);
                wmma::mma_sync(accS[j], alo, bhi, accS[j]);
            }
        }
        // exp in-fragment (elementwise, row-agnostic)
#pragma unroll
        for (int j = 0; j < 4; j++)
#pragma unroll
            for (int e = 0; e < accS[j].num_elements; e++)
                accS[j].x[e] = __expf(accS[j].x[e] * 0.125f);
#pragma unroll
        for (int j = 0; j < 4; j++)
            wmma::store_matrix_sync(sP + (wm * 16) * LDP + wn * 64 + j * 16, accS[j],
                                    LDP, wmma::mem_row_major);
        __syncthreads();

        // rowsum + unnormalized attn write + bf16 split of P
        {
            int r = tid >> 2, part = (tid & 3) * 32;
            float local = 0.0f;
            const size_t abase = (qrow0 + r) * S_ + (size_t)ch * TB + part;
#pragma unroll
            for (int c2 = 0; c2 < 32; c2 += 2) {
                float e0 = sP[r * LDP + part + c2];
                float e1 = sP[r * LDP + part + c2 + 1];
                local += e0 + e1;
                if (attn_out) *(float2*)&attn_out[abase + c2] = make_float2(e0, e1);
                __nv_bfloat16 h0,h1,l0,l1;
                split2(e0, h0, l0); split2(e1, h1, l1);
                sPhi[r * LDPB + part + c2]     = h0;
                sPhi[r * LDPB + part + c2 + 1] = h1;
                sPlo[r * LDPB + part + c2]     = l0;
                sPlo[r * LDPB + part + c2 + 1] = l1;
            }
            atomicAdd(&sSum[r], local);
        }
        __syncthreads();

        // O += P V (3-term)
#pragma unroll
        for (int kk = 0; kk < 8; kk++) {
            ABf ahi, alo;
            wmma::load_matrix_sync(ahi, sPhi + (wm * 16) * LDPB + kk * 16, LDPB);
            wmma::load_matrix_sync(alo, sPlo + (wm * 16) * LDPB + kk * 16, LDPB);
#pragma unroll
            for (int j = 0; j < 2; j++) {
                BBfR bhi, blo;
                wmma::load_matrix_sync(bhi, sVhi + (kk * 16) * LDB16 + wn * 32 + j * 16, LDB16);
                wmma::load_matrix_sync(blo, sVlo + (kk * 16) * LDB16 + wn * 32 + j * 16, LDB16);
                wmma::mma_sync(accO[j], ahi, bhi, accO[j]);
                wmma::mma_sync(accO[j], ahi, blo, accO[j]);
                wmma::mma_sync(accO[j], alo, bhi, accO[j]);
            }
        }
    }
    __syncthreads();

    // stage O in sP (64x64, ld 68), then scale + split to concat hi/lo
#pragma unroll
    for (int j = 0; j < 2; j++)
        wmma::store_matrix_sync(sP + (wm * 16) * LDF32 + wn * 32 + j * 16, accO[j],
                                LDF32, wmma::mem_row_major);
    __syncthreads();

    const int b = bh >> 4, h = bh & 15;
#pragma unroll
    for (int i = tid; i < QB * 32; i += 256) {
        int r = i >> 5, c2 = (i & 31) * 2;
        float inv = 1.0f / sSum[r];
        float o0 = sP[r * LDF32 + c2] * inv;
        float o1 = sP[r * LDF32 + c2 + 1] * inv;
        __nv_bfloat16 h0,h1,l0,l1;
        split2(o0, h0, l0); split2(o1, h1, l1);
        size_t g = ((size_t)b * S_ + (size_t)qb * QB + r) * HID + h * D_ + c2;
        *(__nv_bfloat162*)&cat_hi[g] = __halves2bfloat162(h0, h1);
        *(__nv_bfloat162*)&cat_lo[g] = __halves2bfloat162(l0, l1);
    }
    if (tid < QB) g_invsum[qrow0 + tid] = 1.0f / sSum[tid];
}

// ==========================================================================
// K2b: normalize attn rows: attn[row,:] *= g_invsum[row]. grid = 65536.
// ==========================================================================
__global__ __launch_bounds__(256) void scale_kernel(float* __restrict__ attn_out)
{
    size_t row = blockIdx.x;
    float inv = g_invsum[row];
    float4* p = (float4*)(attn_out + row * S_);
#pragma unroll
    for (int i = threadIdx.x; i < S_ / 4; i += 256) {
        float4 v = p[i];
        v.x *= inv; v.y *= inv; v.z *= inv; v.w *= inv;
        p[i] = v;
    }
}

// ==========================================================================
// K3: out = concat @ Wo (pre-split bf16 operands). grid (32, 16), 2 blk/SM.
// ==========================================================================
__global__ __launch_bounds__(256, 2) void outproj_kernel(float* __restrict__ out)
{
    extern __shared__ char smraw[];
    __nv_bfloat16* sAhi = (__nv_bfloat16*)smraw;
    __nv_bfloat16* sAlo = sAhi + 128 * LDB16;
    __nv_bfloat16* sBhi = sAlo + 128 * LDB16;
    __nv_bfloat16* sBlo = sBhi + 64 * LDB16;

    const int m0 = blockIdx.x * 128;
    const int n0 = blockIdx.y * 64;
    const int tid = threadIdx.x;
    const int warp = tid >> 5;
    const int wm = warp & 3;
    const int wn = warp >> 2;

    CBf acc[2][2];
#pragma unroll
    for (int i = 0; i < 2; i++)
#pragma unroll
        for (int j = 0; j < 2; j++) wmma::fill_fragment(acc[i][j], 0.0f);

    for (int k0 = 0; k0 < HID; k0 += 64) {
#pragma unroll
        for (int i = tid; i < 1024; i += 256) {
            int r = i >> 3, c8 = (i & 7) * 8;
            size_t g = (size_t)(m0 + r) * HID + k0 + c8;
            *(uint4*)&sAhi[r * LDB16 + c8] = *(const uint4*)&cat_hi[g];
            *(uint4*)&sAlo[r * LDB16 + c8] = *(const uint4*)&cat_lo[g];
        }
#pragma unroll
        for (int i = tid; i < 512; i += 256) {
            int r = i >> 3, c8 = (i & 7) * 8;
            size_t g = (size_t)(k0 + r) * HID + n0 + c8;
            *(uint4*)&sBhi[r * LDB16 + c8] = *(const uint4*)&wo_hi[g];
            *(uint4*)&sBlo[r * LDB16 + c8] = *(const uint4*)&wo_lo[g];
        }
        __syncthreads();

#pragma unroll
        for (int kk = 0; kk < 4; kk++) {
            ABf ahi[2], alo[2];
#pragma unroll
            for (int i = 0; i < 2; i++) {
                wmma::load_matrix_sync(ahi[i], sAhi + (wm * 32 + i * 16) * LDB16 + kk * 16, LDB16);
                wmma::load_matrix_sync(alo[i], sAlo + (wm * 32 + i * 16) * LDB16 + kk * 16, LDB16);
            }
#pragma unroll
            for (int j = 0; j < 2; j++) {
                BBfR bhi, blo;
                wmma::load_matrix_sync(bhi, sBhi + (kk * 16) * LDB16 + wn * 32 + j * 16, LDB16);
                wmma::load_matrix_sync(blo, sBlo + (kk * 16) * LDB16 + wn * 32 + j * 16, LDB16);
#pragma unroll
                for (int i = 0; i < 2; i++) {
                    wmma::mma_sync(acc[i][j], ahi[i], bhi, acc[i][j]);
                    wmma::mma_sync(acc[i][j], ahi[i], blo, acc[i][j]);
                    wmma::mma_sync(acc[i][j], alo[i], bhi, acc[i][j]);
                }
            }
        }
        __syncthreads();
    }

    float* obase = out + (size_t)m0 * HID + n0;
#pragma unroll
    for (int i = 0; i < 2; i++)
#pragma unroll
        for (int j = 0; j < 2; j++)
            wmma::store_matrix_sync(obase + (size_t)(wm * 32 + i * 16) * HID + wn * 32 + j * 16,
                                    acc[i][j], HID, wmma::mem_row_major);
}

// ==========================================================================
extern "C" void kernel_launch(void* const* d_in, const int* in_sizes, int n_in,
                              void* d_out, int out_size)
{
    const float* q  = (const float*)d_in[0];
    const float* k  = (const float*)d_in[1];
    const float* v  = (const float*)d_in[2];
    const float* Wq = (const float*)d_in[3];
    const float* Wk = (const float*)d_in[4];
    const float* Wv = (const float*)d_in[5];
    const float* Wo = (const float*)d_in[6];

    float* out  = (float*)d_out;
    float* attn = nullptr;
    const long long OUT_ELEMS  = (long long)MROWS * HID;
    const long long ATTN_ELEMS = (long long)B_ * H_ * S_ * S_;
    if ((long long)out_size >= OUT_ELEMS + ATTN_ELEMS)
        attn = out + OUT_ELEMS;

    const int gemm_smem = (128 + 64) * LDB16 * 2 * 2;        // 55296 bytes
    cudaFuncSetAttribute(proj_kernel,    cudaFuncAttributeMaxDynamicSharedMemorySize, gemm_smem);
    cudaFuncSetAttribute(outproj_kernel, cudaFuncAttributeMaxDynamicSharedMemorySize, gemm_smem);
    cudaFuncSetAttribute(attn_kernel,    cudaFuncAttributeMaxDynamicSharedMemorySize, ATTN_SMEM);

    presplit_kernel<<<4096, 256>>>(q, k, v, Wq, Wk, Wv, Wo);

    dim3 g1(MROWS / 128, 3 * H_);
    proj_kernel<<<g1, 256, gemm_smem>>>();

    dim3 g2(S_ / QB, B_ * H_);
    attn_kernel<<<g2, 256, ATTN_SMEM>>>(attn);

    if (attn) scale_kernel<<<B_ * H_ * S_, 256>>>(attn);

    dim3 g3(MROWS / 128, HID / 64);
    outproj_kernel<<<g3, 256, gemm_smem>>>(out);
}

// round 6
// speedup vs baseline: 3.0959x; 1.0614x over previous
#include <cuda_runtime.h>
#include <cuda_bf16.h>
#include <mma.h>

using namespace nvcuda;

#define B_   2
#define S_   2048
#define H_   16
#define D_   64
#define HID  1024
#define MROWS (B_*S_)          // 4096
#define QB 128
#define TB 64
#define NCH (S_/TB)            // 32
#define XN (MROWS*HID)         // 4,194,304
#define WN (H_*HID*D_)         // 1,048,576

// ---------------- global scratch (static; no allocations) -----------------
__device__ __nv_bfloat16 iq_hi[XN], iq_lo[XN], ik_hi[XN], ik_lo[XN], iv_hi[XN], iv_lo[XN];
__device__ __nv_bfloat16 wq_hi[WN], wq_lo[WN], wk_hi[WN], wk_lo[WN], wv_hi[WN], wv_lo[WN];
__device__ __nv_bfloat16 wo_hi[WN], wo_lo[WN];
__device__ __nv_bfloat16 pq_hi[XN], pq_lo[XN], pk_hi[XN], pk_lo[XN], pv_hi[XN], pv_lo[XN];
__device__ __nv_bfloat16 cat_hi[XN], cat_lo[XN];
__device__ float g_invsum[(size_t)B_*H_*S_];

// ---------------- fragment types ------------------------------------------
typedef wmma::fragment<wmma::matrix_a, 16, 16, 16, __nv_bfloat16, wmma::row_major> ABf;
typedef wmma::fragment<wmma::matrix_b, 16, 16, 16, __nv_bfloat16, wmma::row_major> BBfR;
typedef wmma::fragment<wmma::matrix_b, 16, 16, 16, __nv_bfloat16, wmma::col_major> BBfC;
typedef wmma::fragment<wmma::accumulator, 16, 16, 16, float> CBf;

__device__ __forceinline__ void split2(float x, __nv_bfloat16& hi, __nv_bfloat16& lo) {
    hi = __float2bfloat16(x);
    lo = __float2bfloat16(x - __bfloat162float(hi));
}

#define LDB16 72   // bf16 tile stride (64 + 8)
#define LDF32 68   // f32 tile stride (64 + 4)

// ==========================================================================
// K0: presplit all f32 operands to bf16 hi/lo.
// 4096 blocks x 256 threads x 4 float4 each.
// ==========================================================================
__global__ __launch_bounds__(256) void presplit_kernel(
    const float* __restrict__ q, const float* __restrict__ k, const float* __restrict__ v,
    const float* __restrict__ Wq, const float* __restrict__ Wk, const float* __restrict__ Wv,
    const float* __restrict__ Wo)
{
    int blk = blockIdx.x;
    const float* src; __nv_bfloat16 *hi, *lo; int base;
    if      (blk < 1024) { src = q;  hi = iq_hi; lo = iq_lo; base = blk; }
    else if (blk < 2048) { src = k;  hi = ik_hi; lo = ik_lo; base = blk - 1024; }
    else if (blk < 3072) { src = v;  hi = iv_hi; lo = iv_lo; base = blk - 2048; }
    else if (blk < 3328) { src = Wq; hi = wq_hi; lo = wq_lo; base = blk - 3072; }
    else if (blk < 3584) { src = Wk; hi = wk_hi; lo = wk_lo; base = blk - 3328; }
    else if (blk < 3840) { src = Wv; hi = wv_hi; lo = wv_lo; base = blk - 3584; }
    else                 { src = Wo; hi = wo_hi; lo = wo_lo; base = blk - 3840; }

#pragma unroll
    for (int j = 0; j < 4; j++) {
        size_t i4 = (size_t)base * 1024 + j * 256 + threadIdx.x;
        float4 val = ((const float4*)src)[i4];
        __nv_bfloat16 h0,h1,h2,h3,l0,l1,l2,l3;
        split2(val.x, h0, l0); split2(val.y, h1, l1);
        split2(val.z, h2, l2); split2(val.w, h3, l3);
        ((__nv_bfloat162*)hi)[i4*2]   = __halves2bfloat162(h0, h1);
        ((__nv_bfloat162*)hi)[i4*2+1] = __halves2bfloat162(h2, h3);
        ((__nv_bfloat162*)lo)[i4*2]   = __halves2bfloat162(l0, l1);
        ((__nv_bfloat162*)lo)[i4*2+1] = __halves2bfloat162(l2, l3);
    }
}

// ==========================================================================
// K1: fused QKV projection. grid (32, 48), 256 threads, 2 blocks/SM.
// ==========================================================================
__global__ __launch_bounds__(256, 2) void proj_kernel()
{
    extern __shared__ char smraw[];
    __nv_bfloat16* sAhi = (__nv_bfloat16*)smraw;             // 128*72
    __nv_bfloat16* sAlo = sAhi + 128 * LDB16;
    __nv_bfloat16* sBhi = sAlo + 128 * LDB16;                // 64*72
    __nv_bfloat16* sBlo = sBhi + 64 * LDB16;

    const int pz = blockIdx.y >> 4;
    const int h  = blockIdx.y & 15;
    const __nv_bfloat16* Xhi = (pz == 0) ? iq_hi : (pz == 1) ? ik_hi : iv_hi;
    const __nv_bfloat16* Xlo = (pz == 0) ? iq_lo : (pz == 1) ? ik_lo : iv_lo;
    const __nv_bfloat16* Whi = ((pz == 0) ? wq_hi : (pz == 1) ? wk_hi : wv_hi) + (size_t)h * HID * D_;
    const __nv_bfloat16* Wlo = ((pz == 0) ? wq_lo : (pz == 1) ? wk_lo : wv_lo) + (size_t)h * HID * D_;
    __nv_bfloat16* Ohi = (pz == 0) ? pq_hi : (pz == 1) ? pk_hi : pv_hi;
    __nv_bfloat16* Olo = (pz == 0) ? pq_lo : (pz == 1) ? pk_lo : pv_lo;

    const int m0   = blockIdx.x * 128;
    const int tid  = threadIdx.x;
    const int warp = tid >> 5;
    const int wm   = warp & 3;
    const int wn   = warp >> 2;

    CBf acc[2][2];
#pragma unroll
    for (int i = 0; i < 2; i++)
#pragma unroll
        for (int j = 0; j < 2; j++) wmma::fill_fragment(acc[i][j], 0.0f);

    for (int k0 = 0; k0 < HID; k0 += 64) {
#pragma unroll
        for (int i = tid; i < 1024; i += 256) {
            int r = i >> 3, c8 = (i & 7) * 8;
            size_t g = (size_t)(m0 + r) * HID + k0 + c8;
            *(uint4*)&sAhi[r * LDB16 + c8] = *(const uint4*)&Xhi[g];
            *(uint4*)&sAlo[r * LDB16 + c8] = *(const uint4*)&Xlo[g];
        }
#pragma unroll
        for (int i = tid; i < 512; i += 256) {
            int r = i >> 3, c8 = (i & 7) * 8;
            size_t g = (size_t)(k0 + r) * D_ + c8;
            *(uint4*)&sBhi[r * LDB16 + c8] = *(const uint4*)&Whi[g];
            *(uint4*)&sBlo[r * LDB16 + c8] = *(const uint4*)&Wlo[g];
        }
        __syncthreads();

#pragma unroll
        for (int kk = 0; kk < 4; kk++) {
            ABf ahi[2], alo[2];
#pragma unroll
            for (int i = 0; i < 2; i++) {
                wmma::load_matrix_sync(ahi[i], sAhi + (wm * 32 + i * 16) * LDB16 + kk * 16, LDB16);
                wmma::load_matrix_sync(alo[i], sAlo + (wm * 32 + i * 16) * LDB16 + kk * 16, LDB16);
            }
#pragma unroll
            for (int j = 0; j < 2; j++) {
                BBfR bhi, blo;
                wmma::load_matrix_sync(bhi, sBhi + (kk * 16) * LDB16 + wn * 32 + j * 16, LDB16);
                wmma::load_matrix_sync(blo, sBlo + (kk * 16) * LDB16 + wn * 32 + j * 16, LDB16);
#pragma unroll
                for (int i = 0; i < 2; i++) {
                    wmma::mma_sync(acc[i][j], ahi[i], bhi, acc[i][j]);
                    wmma::mma_sync(acc[i][j], ahi[i], blo, acc[i][j]);
                    wmma::mma_sync(acc[i][j], alo[i], bhi, acc[i][j]);
                }
            }
        }
        __syncthreads();
    }

    float* stage = (float*)smraw;                            // 128*68*4 = 34816 B
#pragma unroll
    for (int i = 0; i < 2; i++)
#pragma unroll
        for (int j = 0; j < 2; j++)
            wmma::store_matrix_sync(stage + (size_t)(wm * 32 + i * 16) * LDF32 + wn * 32 + j * 16,
                                    acc[i][j], LDF32, wmma::mem_row_major);
    __syncthreads();

    const int b  = m0 >> 11;
    const int s0 = m0 & (S_ - 1);
    const size_t orow0 = ((size_t)(b * H_ + h) * S_ + s0);
#pragma unroll
    for (int i = tid; i < 128 * 32; i += 256) {
        int r = i >> 5, c2 = (i & 31) * 2;
        float v0 = stage[r * LDF32 + c2], v1 = stage[r * LDF32 + c2 + 1];
        __nv_bfloat16 h0,h1,l0,l1;
        split2(v0, h0, l0); split2(v1, h1, l1);
        size_t g = (orow0 + r) * D_ + c2;
        *(__nv_bfloat162*)&Ohi[g] = __halves2bfloat162(h0, h1);
        *(__nv_bfloat162*)&Olo[g] = __halves2bfloat162(l0, l1);
    }
}

// ==========================================================================
// K2: one-pass attention. grid (16, 32), 512 threads (16 warps).
// QB=128 query rows per block, TB=64 KV rows per chunk, 32 chunks.
// Warp grid 4x4, warp tile 32x16 for both S and O.
// ==========================================================================
#define ATTN_SMEM 145920

__global__ __launch_bounds__(512) void attn_kernel(float* __restrict__ attn_out)
{
    extern __shared__ char smraw[];
    __nv_bfloat16* sQhi = (__nv_bfloat16*)smraw;             // [128][72]
    __nv_bfloat16* sQlo = sQhi + QB * LDB16;
    __nv_bfloat16* sKhi = sQlo + QB * LDB16;                 // [64][72]
    __nv_bfloat16* sKlo = sKhi + TB * LDB16;
    __nv_bfloat16* sVhi = sKlo + TB * LDB16;
    __nv_bfloat16* sVlo = sVhi + TB * LDB16;
    __nv_bfloat16* sPhi = sVlo + TB * LDB16;                 // [128][72]
    __nv_bfloat16* sPlo = sPhi + QB * LDB16;
    float*         sP   = (float*)(sPlo + QB * LDB16);       // [128][68]
    float*         sSum = sP + QB * LDF32;                   // [128]

    const int bh  = blockIdx.y;
    const int qb  = blockIdx.x;
    const int tid = threadIdx.x;
    const int warp = tid >> 5;
    const int wm = warp & 3;             // 4 row strips of 32
    const int wn = warp >> 2;            // 4 col strips of 16

    const size_t qrow0 = (size_t)bh * S_ + (size_t)qb * QB;
    const size_t krow0 = (size_t)bh * S_;

    // load Q tile (128x64, hi+lo): 1024 uint4 per array
#pragma unroll
    for (int i = tid; i < 1024; i += 512) {
        int r = i >> 3, c8 = (i & 7) * 8;
        size_t g = (qrow0 + r) * D_ + c8;
        *(uint4*)&sQhi[r * LDB16 + c8] = *(const uint4*)&pq_hi[g];
        *(uint4*)&sQlo[r * LDB16 + c8] = *(const uint4*)&pq_lo[g];
    }
    if (tid < QB) sSum[tid] = 0.0f;

    CBf accO[2];
#pragma unroll
    for (int i = 0; i < 2; i++) wmma::fill_fragment(accO[i], 0.0f);

    for (int ch = 0; ch < NCH; ch++) {
        __syncthreads();
        // K/V chunk (64x64 x4 arrays): 512 uint4 each
        {
            int i = tid;
            if (i < 512) {
                int r = i >> 3, c8 = (i & 7) * 8;
                size_t g = (krow0 + (size_t)ch * TB + r) * D_ + c8;
                *(uint4*)&sKhi[r * LDB16 + c8] = *(const uint4*)&pk_hi[g];
                *(uint4*)&sKlo[r * LDB16 + c8] = *(const uint4*)&pk_lo[g];
                *(uint4*)&sVhi[r * LDB16 + c8] = *(const uint4*)&pv_hi[g];
                *(uint4*)&sVlo[r * LDB16 + c8] = *(const uint4*)&pv_lo[g];
            }
        }
        __syncthreads();

        // S = Q K^T (3-term split), warp tile 32x16
        CBf accS[2];
#pragma unroll
        for (int i = 0; i < 2; i++) wmma::fill_fragment(accS[i], 0.0f);
#pragma unroll
        for (int kk = 0; kk < 4; kk++) {
            ABf ahi[2], alo[2];
#pragma unroll
            for (int i = 0; i < 2; i++) {
                wmma::load_matrix_sync(ahi[i], sQhi + (wm * 32 + i * 16) * LDB16 + kk * 16, LDB16);
                wmma::load_matrix_sync(alo[i], sQlo + (wm * 32 + i * 16) * LDB16 + kk * 16, LDB16);
            }
            BBfC bhi, blo;
            wmma::load_matrix_sync(bhi, sKhi + (wn * 16) * LDB16 + kk * 16, LDB16);
            wmma::load_matrix_sync(blo, sKlo + (wn * 16) * LDB16 + kk * 16, LDB16);
#pragma unroll
            for (int i = 0; i < 2; i++) {
                wmma::mma_sync(accS[i], ahi[i], bhi, accS[i]);
                wmma::mma_sync(accS[i], ahi[i], blo, accS[i]);
                wmma::mma_sync(accS[i], alo[i], bhi, accS[i]);
            }
        }
        // exp in-fragment
#pragma unroll
        for (int i = 0; i < 2; i++)
#pragma unroll
            for (int e = 0; e < accS[i].num_elements; e++)
                accS[i].x[e] = __expf(accS[i].x[e] * 0.125f);
#pragma unroll
        for (int i = 0; i < 2; i++)
            wmma::store_matrix_sync(sP + (wm * 32 + i * 16) * LDF32 + wn * 16, accS[i],
                                    LDF32, wmma::mem_row_major);
        __syncthreads();

        // rowsum + unnormalized attn write + bf16 split of P
        {
            int r = tid >> 2, cb = (tid & 3) * 16;
            float local = 0.0f;
            const size_t abase = (qrow0 + r) * S_ + (size_t)ch * TB + cb;
#pragma unroll
            for (int c = 0; c < 16; c += 2) {
                float e0 = sP[r * LDF32 + cb + c];
                float e1 = sP[r * LDF32 + cb + c + 1];
                local += e0 + e1;
                if (attn_out) *(float2*)&attn_out[abase + c] = make_float2(e0, e1);
                __nv_bfloat16 h0,h1,l0,l1;
                split2(e0, h0, l0); split2(e1, h1, l1);
                sPhi[r * LDB16 + cb + c]     = h0;
                sPhi[r * LDB16 + cb + c + 1] = h1;
                sPlo[r * LDB16 + cb + c]     = l0;
                sPlo[r * LDB16 + cb + c + 1] = l1;
            }
            atomicAdd(&sSum[r], local);
        }
        __syncthreads();

        // O += P V (3-term), warp tile 32x16
#pragma unroll
        for (int kk = 0; kk < 4; kk++) {
            ABf ahi[2], alo[2];
#pragma unroll
            for (int i = 0; i < 2; i++) {
                wmma::load_matrix_sync(ahi[i], sPhi + (wm * 32 + i * 16) * LDB16 + kk * 16, LDB16);
                wmma::load_matrix_sync(alo[i], sPlo + (wm * 32 + i * 16) * LDB16 + kk * 16, LDB16);
            }
            BBfR bhi, blo;
            wmma::load_matrix_sync(bhi, sVhi + (kk * 16) * LDB16 + wn * 16, LDB16);
            wmma::load_matrix_sync(blo, sVlo + (kk * 16) * LDB16 + wn * 16, LDB16);
#pragma unroll
            for (int i = 0; i < 2; i++) {
                wmma::mma_sync(accO[i], ahi[i], bhi, accO[i]);
                wmma::mma_sync(accO[i], ahi[i], blo, accO[i]);
                wmma::mma_sync(accO[i], alo[i], bhi, accO[i]);
            }
        }
    }
    __syncthreads();

    // stage O (128x64) in sP, then scale + split to concat hi/lo
#pragma unroll
    for (int i = 0; i < 2; i++)
        wmma::store_matrix_sync(sP + (wm * 32 + i * 16) * LDF32 + wn * 16, accO[i],
                                LDF32, wmma::mem_row_major);
    __syncthreads();

    const int b = bh >> 4, h = bh & 15;
    {
        int r = tid >> 2, cb = (tid & 3) * 16;
        float inv = 1.0f / sSum[r];
        size_t gbase = ((size_t)b * S_ + (size_t)qb * QB + r) * HID + h * D_ + cb;
#pragma unroll
        for (int c = 0; c < 16; c += 2) {
            float o0 = sP[r * LDF32 + cb + c] * inv;
            float o1 = sP[r * LDF32 + cb + c + 1] * inv;
            __nv_bfloat16 h0,h1,l0,l1;
            split2(o0, h0, l0); split2(o1, h1, l1);
            *(__nv_bfloat162*)&cat_hi[gbase + c] = __halves2bfloat162(h0, h1);
            *(__nv_bfloat162*)&cat_lo[gbase + c] = __halves2bfloat162(l0, l1);
        }
    }
    if (tid < QB) g_invsum[qrow0 + tid] = 1.0f / sSum[tid];
}

// ==========================================================================
// K3: FUSED out-projection + attn normalization. grid (1024), 256 threads.
//   blocks [0,512):   out = concat @ Wo  (tensor blocks, tile 128x64)
//   blocks [512,1024): attn rows *= invsum (DRAM-streaming blocks, 128 rows ea)
// Both depend only on attn_kernel outputs; running them concurrently
// overlaps tensor work with DRAM streaming.
// ==========================================================================
__global__ __launch_bounds__(256, 2) void outproj_scale_kernel(
    float* __restrict__ out, float* __restrict__ attn_out)
{
    const int bx  = blockIdx.x;
    const int tid = threadIdx.x;

    if (bx >= 512) {
        // ---- scale branch: 128 rows of attn per block ----
        if (!attn_out) return;
        const size_t row0 = (size_t)(bx - 512) * 128;
        float4* p = (float4*)(attn_out + row0 * S_);
#pragma unroll 4
        for (int i = tid; i < 128 * (S_ / 4); i += 256) {
            float inv = g_invsum[row0 + (i >> 9)];
            float4 v = p[i];
            v.x *= inv; v.y *= inv; v.z *= inv; v.w *= inv;
            p[i] = v;
        }
        return;
    }

    // ---- outproj branch ----
    extern __shared__ char smraw[];
    __nv_bfloat16* sAhi = (__nv_bfloat16*)smraw;
    __nv_bfloat16* sAlo = sAhi + 128 * LDB16;
    __nv_bfloat16* sBhi = sAlo + 128 * LDB16;
    __nv_bfloat16* sBlo = sBhi + 64 * LDB16;

    const int m0 = (bx & 31) * 128;
    const int n0 = (bx >> 5) * 64;
    const int warp = tid >> 5;
    const int wm = warp & 3;
    const int wn = warp >> 2;

    CBf acc[2][2];
#pragma unroll
    for (int i = 0; i < 2; i++)
#pragma unroll
        for (int j = 0; j < 2; j++) wmma::fill_fragment(acc[i][j], 0.0f);

    for (int k0 = 0; k0 < HID; k0 += 64) {
#pragma unroll
        for (int i = tid; i < 1024; i += 256) {
            int r = i >> 3, c8 = (i & 7) * 8;
            size_t g = (size_t)(m0 + r) * HID + k0 + c8;
            *(uint4*)&sAhi[r * LDB16 + c8] = *(const uint4*)&cat_hi[g];
            *(uint4*)&sAlo[r * LDB16 + c8] = *(const uint4*)&cat_lo[g];
        }
#pragma unroll
        for (int i = tid; i < 512; i += 256) {
            int r = i >> 3, c8 = (i & 7) * 8;
            size_t g = (size_t)(k0 + r) * HID + n0 + c8;
            *(uint4*)&sBhi[r * LDB16 + c8] = *(const uint4*)&wo_hi[g];
            *(uint4*)&sBlo[r * LDB16 + c8] = *(const uint4*)&wo_lo[g];
        }
        __syncthreads();

#pragma unroll
        for (int kk = 0; kk < 4; kk++) {
            ABf ahi[2], alo[2];
#pragma unroll
            for (int i = 0; i < 2; i++) {
                wmma::load_matrix_sync(ahi[i], sAhi + (wm * 32 + i * 16) * LDB16 + kk * 16, LDB16);
                wmma::load_matrix_sync(alo[i], sAlo + (wm * 32 + i * 16) * LDB16 + kk * 16, LDB16);
            }
#pragma unroll
            for (int j = 0; j < 2; j++) {
                BBfR bhi, blo;
                wmma::load_matrix_sync(bhi, sBhi + (kk * 16) * LDB16 + wn * 32 + j * 16, LDB16);
                wmma::load_matrix_sync(blo, sBlo + (kk * 16) * LDB16 + wn * 32 + j * 16, LDB16);
#pragma unroll
                for (int i = 0; i < 2; i++) {
                    wmma::mma_sync(acc[i][j], ahi[i], bhi, acc[i][j]);
                    wmma::mma_sync(acc[i][j], ahi[i], blo, acc[i][j]);
                    wmma::mma_sync(acc[i][j], alo[i], bhi, acc[i][j]);
                }
            }
        }
        __syncthreads();
    }

    float* obase = out + (size_t)m0 * HID + n0;
#pragma unroll
    for (int i = 0; i < 2; i++)
#pragma unroll
        for (int j = 0; j < 2; j++)
            wmma::store_matrix_sync(obase + (size_t)(wm * 32 + i * 16) * HID + wn * 32 + j * 16,
                                    acc[i][j], HID, wmma::mem_row_major);
}

// ==========================================================================
extern "C" void kernel_launch(void* const* d_in, const int* in_sizes, int n_in,
                              void* d_out, int out_size)
{
    const float* q  = (const float*)d_in[0];
    const float* k  = (const float*)d_in[1];
    const float* v  = (const float*)d_in[2];
    const float* Wq = (const float*)d_in[3];
    const float* Wk = (const float*)d_in[4];
    const float* Wv = (const float*)d_in[5];
    const float* Wo = (const float*)d_in[6];

    float* out  = (float*)d_out;
    float* attn = nullptr;
    const long long OUT_ELEMS  = (long long)MROWS * HID;
    const long long ATTN_ELEMS = (long long)B_ * H_ * S_ * S_;
    if ((long long)out_size >= OUT_ELEMS + ATTN_ELEMS)
        attn = out + OUT_ELEMS;

    const int gemm_smem = (128 + 64) * LDB16 * 2 * 2;        // 55296 bytes
    cudaFuncSetAttribute(proj_kernel,          cudaFuncAttributeMaxDynamicSharedMemorySize, gemm_smem);
    cudaFuncSetAttribute(outproj_scale_kernel, cudaFuncAttributeMaxDynamicSharedMemorySize, gemm_smem);
    cudaFuncSetAttribute(attn_kernel,          cudaFuncAttributeMaxDynamicSharedMemorySize, ATTN_SMEM);

    presplit_kernel<<<4096, 256>>>(q, k, v, Wq, Wk, Wv, Wo);

    dim3 g1(MROWS / 128, 3 * H_);
    proj_kernel<<<g1, 256, gemm_smem>>>();

    dim3 g2(S_ / QB, B_ * H_);
    attn_kernel<<<g2, 512, ATTN_SMEM>>>(attn);

    outproj_scale_kernel<<<1024, 256, gemm_smem>>>(out, attn);
}

// round 8
// speedup vs baseline: 3.2043x; 1.0350x over previous
#include <cuda_runtime.h>
#include <cuda_bf16.h>
#include <mma.h>
#include <cstdint>
#include <cstddef>

using namespace nvcuda;

#define B_   2
#define S_   2048
#define H_   16
#define D_   64
#define HID  1024
#define MROWS (B_*S_)          // 4096
#define QB 128
#define TB 64
#define NCH (S_/TB)            // 32
#define XN (MROWS*HID)         // 4,194,304
#define WN (H_*HID*D_)         // 1,048,576

// ---------------- global scratch (static; no allocations) -----------------
__device__ __nv_bfloat16 iq_hi[XN], iq_lo[XN], ik_hi[XN], ik_lo[XN], iv_hi[XN], iv_lo[XN];
__device__ __nv_bfloat16 wq_hi[WN], wq_lo[WN], wk_hi[WN], wk_lo[WN], wv_hi[WN], wv_lo[WN];
__device__ __nv_bfloat16 wo_hi[WN], wo_lo[WN];
__device__ __nv_bfloat16 pq_hi[XN], pq_lo[XN], pk_hi[XN], pk_lo[XN], pv_hi[XN], pv_lo[XN];
__device__ __nv_bfloat16 cat_hi[XN], cat_lo[XN];
__device__ float g_invsum[(size_t)B_*H_*S_];

// ---------------- fragment types ------------------------------------------
typedef wmma::fragment<wmma::matrix_a, 16, 16, 16, __nv_bfloat16, wmma::row_major> ABf;
typedef wmma::fragment<wmma::matrix_b, 16, 16, 16, __nv_bfloat16, wmma::row_major> BBfR;
typedef wmma::fragment<wmma::matrix_b, 16, 16, 16, __nv_bfloat16, wmma::col_major> BBfC;
typedef wmma::fragment<wmma::accumulator, 16, 16, 16, float> CBf;

__device__ __forceinline__ void split2(float x, __nv_bfloat16& hi, __nv_bfloat16& lo) {
    hi = __float2bfloat16(x);
    lo = __float2bfloat16(x - __bfloat162float(hi));
}

__device__ __forceinline__ void cp16(uint32_t saddr, const void* gaddr) {
    asm volatile("cp.async.cg.shared.global [%0], [%1], 16;\n" :: "r"(saddr), "l"(gaddr));
}
#define CP_COMMIT() asm volatile("cp.async.commit_group;\n" ::: "memory")
#define CP_WAIT1()  asm volatile("cp.async.wait_group 1;\n" ::: "memory")
#define CP_WAIT0()  asm volatile("cp.async.wait_group 0;\n" ::: "memory")

#define LDB16 72   // bf16 tile stride (64 + 8)
#define LDF32 68   // f32 tile stride (64 + 4)

// ==========================================================================
// K0: presplit all f32 operands to bf16 hi/lo.
// ==========================================================================
__global__ __launch_bounds__(256) void presplit_kernel(
    const float* __restrict__ q, const float* __restrict__ k, const float* __restrict__ v,
    const float* __restrict__ Wq, const float* __restrict__ Wk, const float* __restrict__ Wv,
    const float* __restrict__ Wo)
{
    int blk = blockIdx.x;
    const float* src; __nv_bfloat16 *hi, *lo; int base;
    if      (blk < 1024) { src = q;  hi = iq_hi; lo = iq_lo; base = blk; }
    else if (blk < 2048) { src = k;  hi = ik_hi; lo = ik_lo; base = blk - 1024; }
    else if (blk < 3072) { src = v;  hi = iv_hi; lo = iv_lo; base = blk - 2048; }
    else if (blk < 3328) { src = Wq; hi = wq_hi; lo = wq_lo; base = blk - 3072; }
    else if (blk < 3584) { src = Wk; hi = wk_hi; lo = wk_lo; base = blk - 3328; }
    else if (blk < 3840) { src = Wv; hi = wv_hi; lo = wv_lo; base = blk - 3584; }
    else                 { src = Wo; hi = wo_hi; lo = wo_lo; base = blk - 3840; }

#pragma unroll
    for (int j = 0; j < 4; j++) {
        size_t i4 = (size_t)base * 1024 + j * 256 + threadIdx.x;
        float4 val = ((const float4*)src)[i4];
        __nv_bfloat16 h0,h1,h2,h3,l0,l1,l2,l3;
        split2(val.x, h0, l0); split2(val.y, h1, l1);
        split2(val.z, h2, l2); split2(val.w, h3, l3);
        ((__nv_bfloat162*)hi)[i4*2]   = __halves2bfloat162(h0, h1);
        ((__nv_bfloat162*)hi)[i4*2+1] = __halves2bfloat162(h2, h3);
        ((__nv_bfloat162*)lo)[i4*2]   = __halves2bfloat162(l0, l1);
        ((__nv_bfloat162*)lo)[i4*2+1] = __halves2bfloat162(l2, l3);
    }
}

// ==========================================================================
// K1: fused QKV projection. grid (32, 48), 256 threads, 2 blocks/SM.
// ==========================================================================
__global__ __launch_bounds__(256, 2) void proj_kernel()
{
    extern __shared__ char smraw[];
    __nv_bfloat16* sAhi = (__nv_bfloat16*)smraw;             // 128*72
    __nv_bfloat16* sAlo = sAhi + 128 * LDB16;
    __nv_bfloat16* sBhi = sAlo + 128 * LDB16;                // 64*72
    __nv_bfloat16* sBlo = sBhi + 64 * LDB16;

    const int pz = blockIdx.y >> 4;
    const int h  = blockIdx.y & 15;
    const __nv_bfloat16* Xhi = (pz == 0) ? iq_hi : (pz == 1) ? ik_hi : iv_hi;
    const __nv_bfloat16* Xlo = (pz == 0) ? iq_lo : (pz == 1) ? ik_lo : iv_lo;
    const __nv_bfloat16* Whi = ((pz == 0) ? wq_hi : (pz == 1) ? wk_hi : wv_hi) + (size_t)h * HID * D_;
    const __nv_bfloat16* Wlo = ((pz == 0) ? wq_lo : (pz == 1) ? wk_lo : wv_lo) + (size_t)h * HID * D_;
    __nv_bfloat16* Ohi = (pz == 0) ? pq_hi : (pz == 1) ? pk_hi : pv_hi;
    __nv_bfloat16* Olo = (pz == 0) ? pq_lo : (pz == 1) ? pk_lo : pv_lo;

    const int m0   = blockIdx.x * 128;
    const int tid  = threadIdx.x;
    const int warp = tid >> 5;
    const int wm   = warp & 3;
    const int wn   = warp >> 2;

    CBf acc[2][2];
#pragma unroll
    for (int i = 0; i < 2; i++)
#pragma unroll
        for (int j = 0; j < 2; j++) wmma::fill_fragment(acc[i][j], 0.0f);

    for (int k0 = 0; k0 < HID; k0 += 64) {
#pragma unroll
        for (int i = tid; i < 1024; i += 256) {
            int r = i >> 3, c8 = (i & 7) * 8;
            size_t g = (size_t)(m0 + r) * HID + k0 + c8;
            *(uint4*)&sAhi[r * LDB16 + c8] = *(const uint4*)&Xhi[g];
            *(uint4*)&sAlo[r * LDB16 + c8] = *(const uint4*)&Xlo[g];
        }
#pragma unroll
        for (int i = tid; i < 512; i += 256) {
            int r = i >> 3, c8 = (i & 7) * 8;
            size_t g = (size_t)(k0 + r) * D_ + c8;
            *(uint4*)&sBhi[r * LDB16 + c8] = *(const uint4*)&Whi[g];
            *(uint4*)&sBlo[r * LDB16 + c8] = *(const uint4*)&Wlo[g];
        }
        __syncthreads();

#pragma unroll
        for (int kk = 0; kk < 4; kk++) {
            ABf ahi[2], alo[2];
#pragma unroll
            for (int i = 0; i < 2; i++) {
                wmma::load_matrix_sync(ahi[i], sAhi + (wm * 32 + i * 16) * LDB16 + kk * 16, LDB16);
                wmma::load_matrix_sync(alo[i], sAlo + (wm * 32 + i * 16) * LDB16 + kk * 16, LDB16);
            }
#pragma unroll
            for (int j = 0; j < 2; j++) {
                BBfR bhi, blo;
                wmma::load_matrix_sync(bhi, sBhi + (kk * 16) * LDB16 + wn * 32 + j * 16, LDB16);
                wmma::load_matrix_sync(blo, sBlo + (kk * 16) * LDB16 + wn * 32 + j * 16, LDB16);
#pragma unroll
                for (int i = 0; i < 2; i++) {
                    wmma::mma_sync(acc[i][j], ahi[i], bhi, acc[i][j]);
                    wmma::mma_sync(acc[i][j], ahi[i], blo, acc[i][j]);
                    wmma::mma_sync(acc[i][j], alo[i], bhi, acc[i][j]);
                }
            }
        }
        __syncthreads();
    }

    float* stage = (float*)smraw;                            // 128*68*4 = 34816 B
#pragma unroll
    for (int i = 0; i < 2; i++)
#pragma unroll
        for (int j = 0; j < 2; j++)
            wmma::store_matrix_sync(stage + (size_t)(wm * 32 + i * 16) * LDF32 + wn * 32 + j * 16,
                                    acc[i][j], LDF32, wmma::mem_row_major);
    __syncthreads();

    const int b  = m0 >> 11;
    const int s0 = m0 & (S_ - 1);
    const size_t orow0 = ((size_t)(b * H_ + h) * S_ + s0);
#pragma unroll
    for (int i = tid; i < 128 * 32; i += 256) {
        int r = i >> 5, c2 = (i & 31) * 2;
        float v0 = stage[r * LDF32 + c2], v1 = stage[r * LDF32 + c2 + 1];
        __nv_bfloat16 h0,h1,l0,l1;
        split2(v0, h0, l0); split2(v1, h1, l1);
        size_t g = (orow0 + r) * D_ + c2;
        *(__nv_bfloat162*)&Ohi[g] = __halves2bfloat162(h0, h1);
        *(__nv_bfloat162*)&Olo[g] = __halves2bfloat162(l0, l1);
    }
}

// ==========================================================================
// K2: one-pass attention w/ cp.async double-buffered K/V.
// grid (16, 32), 512 threads (16 warps). Warp grid 4x4, warp tile 32x16.
// ==========================================================================
#define KVARR (TB*LDB16)          // 4608 elems per array
#define KVBUF (4*KVARR)           // K hi | K lo | V hi | V lo
#define ATTN_SMEM 182784

__global__ __launch_bounds__(512) void attn_kernel(float* __restrict__ attn_out)
{
    extern __shared__ char smraw[];
    __nv_bfloat16* sQhi = (__nv_bfloat16*)smraw;             // [128][72]
    __nv_bfloat16* sQlo = sQhi + QB * LDB16;
    __nv_bfloat16* sKV  = sQlo + QB * LDB16;                 // 2 * KVBUF
    __nv_bfloat16* sPhi = sKV + 2 * KVBUF;                   // [128][72]
    __nv_bfloat16* sPlo = sPhi + QB * LDB16;
    float*         sP   = (float*)(sPlo + QB * LDB16);       // [128][68]
    float*         sSum = sP + QB * LDF32;                   // [128]

    const int bh  = blockIdx.y;
    const int qb  = blockIdx.x;
    const int tid = threadIdx.x;
    const int warp = tid >> 5;
    const int wm = warp & 3;             // 4 row strips of 32
    const int wn = warp >> 2;            // 4 col strips of 16

    const size_t qrow0 = (size_t)bh * S_ + (size_t)qb * QB;
    const size_t krow0 = (size_t)bh * S_;

    // per-thread K/V load slot: 512 threads cover 64 rows x 8 uint4
    const int lr = tid >> 3, lc8 = (tid & 7) * 8;
    const uint32_t kv_base = (uint32_t)__cvta_generic_to_shared(sKV);
    const uint32_t kv_slot = (uint32_t)((lr * LDB16 + lc8) * 2);

    // issue chunk 0 loads (buffer 0)
    {
        size_t g = (krow0 + lr) * D_ + lc8;
        uint32_t s = kv_base + kv_slot;
        cp16(s,                &pk_hi[g]);
        cp16(s + KVARR*2,      &pk_lo[g]);
        cp16(s + 2*KVARR*2,    &pv_hi[g]);
        cp16(s + 3*KVARR*2,    &pv_lo[g]);
        CP_COMMIT();
    }

    // load Q tile (128x64, hi+lo)
#pragma unroll
    for (int i = tid; i < 1024; i += 512) {
        int r = i >> 3, c8 = (i & 7) * 8;
        size_t g = (qrow0 + r) * D_ + c8;
        *(uint4*)&sQhi[r * LDB16 + c8] = *(const uint4*)&pq_hi[g];
        *(uint4*)&sQlo[r * LDB16 + c8] = *(const uint4*)&pq_lo[g];
    }
    if (tid < QB) sSum[tid] = 0.0f;

    CBf accO[2];
#pragma unroll
    for (int i = 0; i < 2; i++) wmma::fill_fragment(accO[i], 0.0f);

    for (int ch = 0; ch < NCH; ch++) {
        const int cur = ch & 1;
        __nv_bfloat16* bKhi = sKV + cur * KVBUF;
        __nv_bfloat16* bKlo = bKhi + KVARR;
        __nv_bfloat16* bVhi = bKhi + 2 * KVARR;
        __nv_bfloat16* bVlo = bKhi + 3 * KVARR;

        // issue next chunk into the other buffer, then ensure current is done
        if (ch + 1 < NCH) {
            size_t g = (krow0 + (size_t)(ch + 1) * TB + lr) * D_ + lc8;
            uint32_t s = kv_base + (uint32_t)((1 - cur) * KVBUF * 2) + kv_slot;
            cp16(s,             &pk_hi[g]);
            cp16(s + KVARR*2,   &pk_lo[g]);
            cp16(s + 2*KVARR*2, &pv_hi[g]);
            cp16(s + 3*KVARR*2, &pv_lo[g]);
            CP_COMMIT();
            CP_WAIT1();
        } else {
            CP_WAIT0();
        }
        __syncthreads();

        // S = Q K^T (3-term split), warp tile 32x16
        CBf accS[2];
#pragma unroll
        for (int i = 0; i < 2; i++) wmma::fill_fragment(accS[i], 0.0f);
#pragma unroll
        for (int kk = 0; kk < 4; kk++) {
            ABf ahi[2], alo[2];
#pragma unroll
            for (int i = 0; i < 2; i++) {
                wmma::load_matrix_sync(ahi[i], sQhi + (wm * 32 + i * 16) * LDB16 + kk * 16, LDB16);
                wmma::load_matrix_sync(alo[i], sQlo + (wm * 32 + i * 16) * LDB16 + kk * 16, LDB16);
            }
            BBfC bhi, blo;
            wmma::load_matrix_sync(bhi, bKhi + (wn * 16) * LDB16 + kk * 16, LDB16);
            wmma::load_matrix_sync(blo, bKlo + (wn * 16) * LDB16 + kk * 16, LDB16);
#pragma unroll
            for (int i = 0; i < 2; i++) {
                wmma::mma_sync(accS[i], ahi[i], bhi, accS[i]);
                wmma::mma_sync(accS[i], ahi[i], blo, accS[i]);
                wmma::mma_sync(accS[i], alo[i], bhi, accS[i]);
            }
        }
        // exp in-fragment
#pragma unroll
        for (int i = 0; i < 2; i++)
#pragma unroll
            for (int e = 0; e < accS[i].num_elements; e++)
                accS[i].x[e] = __expf(accS[i].x[e] * 0.125f);
#pragma unroll
        for (int i = 0; i < 2; i++)
            wmma::store_matrix_sync(sP + (wm * 32 + i * 16) * LDF32 + wn * 16, accS[i],
                                    LDF32, wmma::mem_row_major);
        __syncthreads();

        // rowsum + unnormalized attn write + bf16 split of P
        {
            int r = tid >> 2, cb = (tid & 3) * 16;
            float local = 0.0f;
            const size_t abase = (qrow0 + r) * S_ + (size_t)ch * TB + cb;
#pragma unroll
            for (int c = 0; c < 16; c += 2) {
                float e0 = sP[r * LDF32 + cb + c];
                float e1 = sP[r * LDF32 + cb + c + 1];
                local += e0 + e1;
                if (attn_out) *(float2*)&attn_out[abase + c] = make_float2(e0, e1);
                __nv_bfloat16 h0,h1,l0,l1;
                split2(e0, h0, l0); split2(e1, h1, l1);
                sPhi[r * LDB16 + cb + c]     = h0;
                sPhi[r * LDB16 + cb + c + 1] = h1;
                sPlo[r * LDB16 + cb + c]     = l0;
                sPlo[r * LDB16 + cb + c + 1] = l1;
            }
            atomicAdd(&sSum[r], local);
        }
        __syncthreads();

        // O += P V (3-term), warp tile 32x16
#pragma unroll
        for (int kk = 0; kk < 4; kk++) {
            ABf ahi[2], alo[2];
#pragma unroll
            for (int i = 0; i < 2; i++) {
                wmma::load_matrix_sync(ahi[i], sPhi + (wm * 32 + i * 16) * LDB16 + kk * 16, LDB16);
                wmma::load_matrix_sync(alo[i], sPlo + (wm * 32 + i * 16) * LDB16 + kk * 16, LDB16);
            }
            BBfR bhi, blo;
            wmma::load_matrix_sync(bhi, bVhi + (kk * 16) * LDB16 + wn * 16, LDB16);
            wmma::load_matrix_sync(blo, bVlo + (kk * 16) * LDB16 + wn * 16, LDB16);
#pragma unroll
            for (int i = 0; i < 2; i++) {
                wmma::mma_sync(accO[i], ahi[i], bhi, accO[i]);
                wmma::mma_sync(accO[i], ahi[i], blo, accO[i]);
                wmma::mma_sync(accO[i], alo[i], bhi, accO[i]);
            }
        }
        __syncthreads();   // protect KV buffer + sP for next chunk
    }

    // stage O (128x64) in sP, then scale + split to concat hi/lo
#pragma unroll
    for (int i = 0; i < 2; i++)
        wmma::store_matrix_sync(sP + (wm * 32 + i * 16) * LDF32 + wn * 16, accO[i],
                                LDF32, wmma::mem_row_major);
    __syncthreads();

    const int b = bh >> 4, h = bh & 15;
    {
        int r = tid >> 2, cb = (tid & 3) * 16;
        float inv = 1.0f / sSum[r];
        size_t gbase = ((size_t)b * S_ + (size_t)qb * QB + r) * HID + h * D_ + cb;
#pragma unroll
        for (int c = 0; c < 16; c += 2) {
            float o0 = sP[r * LDF32 + cb + c] * inv;
            float o1 = sP[r * LDF32 + cb + c + 1] * inv;
            __nv_bfloat16 h0,h1,l0,l1;
            split2(o0, h0, l0); split2(o1, h1, l1);
            *(__nv_bfloat162*)&cat_hi[gbase + c] = __halves2bfloat162(h0, h1);
            *(__nv_bfloat162*)&cat_lo[gbase + c] = __halves2bfloat162(l0, l1);
        }
    }
    if (tid < QB) g_invsum[qrow0 + tid] = 1.0f / sSum[tid];
}

// ==========================================================================
// K3: FUSED out-projection + attn normalization, PARITY-INTERLEAVED.
//   even blocks: out = concat @ Wo  (512 tensor blocks, tile 128x64)
//   odd  blocks: attn rows *= invsum (512 DRAM-streaming blocks, 128 rows ea)
// ==========================================================================
__global__ __launch_bounds__(256, 2) void outproj_scale_kernel(
    float* __restrict__ out, float* __restrict__ attn_out)
{
    const int bx  = blockIdx.x;
    const int idx = bx >> 1;
    const int tid = threadIdx.x;

    if (bx & 1) {
        // ---- scale branch: 128 rows of attn per block ----
        if (!attn_out) return;
        const size_t row0 = (size_t)idx * 128;
        float4* p = (float4*)(attn_out + row0 * S_);
#pragma unroll 4
        for (int i = tid; i < 128 * (S_ / 4); i += 256) {
            float inv = g_invsum[row0 + (i >> 9)];
            float4 v = p[i];
            v.x *= inv; v.y *= inv; v.z *= inv; v.w *= inv;
            p[i] = v;
        }
        return;
    }

    // ---- outproj branch ----
    extern __shared__ char smraw[];
    __nv_bfloat16* sAhi = (__nv_bfloat16*)smraw;
    __nv_bfloat16* sAlo = sAhi + 128 * LDB16;
    __nv_bfloat16* sBhi = sAlo + 128 * LDB16;
    __nv_bfloat16* sBlo = sBhi + 64 * LDB16;

    const int m0 = (idx & 31) * 128;
    const int n0 = (idx >> 5) * 64;
    const int warp = tid >> 5;
    const int wm = warp & 3;
    const int wn = warp >> 2;

    CBf acc[2][2];
#pragma unroll
    for (int i = 0; i < 2; i++)
#pragma unroll
        for (int j = 0; j < 2; j++) wmma::fill_fragment(acc[i][j], 0.0f);

    for (int k0 = 0; k0 < HID; k0 += 64) {
#pragma unroll
        for (int i = tid; i < 1024; i += 256) {
            int r = i >> 3, c8 = (i & 7) * 8;
            size_t g = (size_t)(m0 + r) * HID + k0 + c8;
            *(uint4*)&sAhi[r * LDB16 + c8] = *(const uint4*)&cat_hi[g];
            *(uint4*)&sAlo[r * LDB16 + c8] = *(const uint4*)&cat_lo[g];
        }
#pragma unroll
        for (int i = tid; i < 512; i += 256) {
            int r = i >> 3, c8 = (i & 7) * 8;
            size_t g = (size_t)(k0 + r) * HID + n0 + c8;
            *(uint4*)&sBhi[r * LDB16 + c8] = *(const uint4*)&wo_hi[g];
            *(uint4*)&sBlo[r * LDB16 + c8] = *(const uint4*)&wo_lo[g];
        }
        __syncthreads();

#pragma unroll
        for (int kk = 0; kk < 4; kk++) {
            ABf ahi[2], alo[2];
#pragma unroll
            for (int i = 0; i < 2; i++) {
                wmma::load_matrix_sync(ahi[i], sAhi + (wm * 32 + i * 16) * LDB16 + kk * 16, LDB16);
                wmma::load_matrix_sync(alo[i], sAlo + (wm * 32 + i * 16) * LDB16 + kk * 16, LDB16);
            }
#pragma unroll
            for (int j = 0; j < 2; j++) {
                BBfR bhi, blo;
                wmma::load_matrix_sync(bhi, sBhi + (kk * 16) * LDB16 + wn * 32 + j * 16, LDB16);
                wmma::load_matrix_sync(blo, sBlo + (kk * 16) * LDB16 + wn * 32 + j * 16, LDB16);
#pragma unroll
                for (int i = 0; i < 2; i++) {
                    wmma::mma_sync(acc[i][j], ahi[i], bhi, acc[i][j]);
                    wmma::mma_sync(acc[i][j], ahi[i], blo, acc[i][j]);
                    wmma::mma_sync(acc[i][j], alo[i], bhi, acc[i][j]);
                }
            }
        }
        __syncthreads();
    }

    float* obase = out + (size_t)m0 * HID + n0;
#pragma unroll
    for (int i = 0; i < 2; i++)
#pragma unroll
        for (int j = 0; j < 2; j++)
            wmma::store_matrix_sync(obase + (size_t)(wm * 32 + i * 16) * HID + wn * 32 + j * 16,
                                    acc[i][j], HID, wmma::mem_row_major);
}

// ==========================================================================
extern "C" void kernel_launch(void* const* d_in, const int* in_sizes, int n_in,
                              void* d_out, int out_size)
{
    const float* q  = (const float*)d_in[0];
    const float* k  = (const float*)d_in[1];
    const float* v  = (const float*)d_in[2];
    const float* Wq = (const float*)d_in[3];
    const float* Wk = (const float*)d_in[4];
    const float* Wv = (const float*)d_in[5];
    const float* Wo = (const float*)d_in[6];

    float* out  = (float*)d_out;
    float* attn = nullptr;
    const long long OUT_ELEMS  = (long long)MROWS * HID;
    const long long ATTN_ELEMS = (long long)B_ * H_ * S_ * S_;
    if ((long long)out_size >= OUT_ELEMS + ATTN_ELEMS)
        attn = out + OUT_ELEMS;

    const int gemm_smem = (128 + 64) * LDB16 * 2 * 2;        // 55296 bytes
    cudaFuncSetAttribute(proj_kernel,          cudaFuncAttributeMaxDynamicSharedMemorySize, gemm_smem);
    cudaFuncSetAttribute(outproj_scale_kernel, cudaFuncAttributeMaxDynamicSharedMemorySize, gemm_smem);
    cudaFuncSetAttribute(attn_kernel,          cudaFuncAttributeMaxDynamicSharedMemorySize, ATTN_SMEM);

    presplit_kernel<<<4096, 256>>>(q, k, v, Wq, Wk, Wv, Wo);

    dim3 g1(MROWS / 128, 3 * H_);
    proj_kernel<<<g1, 256, gemm_smem>>>();

    dim3 g2(S_ / QB, B_ * H_);
    attn_kernel<<<g2, 512, ATTN_SMEM>>>(attn);

    outproj_scale_kernel<<<1024, 256, gemm_smem>>>(out, attn);
}

// round 11
// speedup vs baseline: 4.2606x; 1.3297x over previous
#include <cuda_runtime.h>
#include <cuda_bf16.h>
#include <mma.h>
#include <cstdint>
#include <cstddef>

using namespace nvcuda;

#define B_   2
#define S_   2048
#define H_   16
#define D_   64
#define HID  1024
#define MROWS (B_*S_)          // 4096
#define XN (MROWS*HID)         // 4,194,304
#define WN (H_*HID*D_)         // 1,048,576

// ---------------- global scratch (static; no allocations) -----------------
__device__ __nv_bfloat16 iq_hi[XN], iq_lo[XN], ik_hi[XN], ik_lo[XN], iv_hi[XN], iv_lo[XN];
__device__ __nv_bfloat16 wq_hi[WN], wq_lo[WN], wk_hi[WN], wk_lo[WN], wv_hi[WN], wv_lo[WN];
__device__ __nv_bfloat16 wo_hi[WN], wo_lo[WN];
__device__ __nv_bfloat16 pq_hi[XN], pq_lo[XN], pk_hi[XN], pk_lo[XN], pv_hi[XN], pv_lo[XN];
__device__ __nv_bfloat16 cat_hi[XN], cat_lo[XN];
__device__ float g_invsum[(size_t)B_*H_*S_];

// ---------------- wmma fragment types (proj / outproj) --------------------
typedef wmma::fragment<wmma::matrix_a, 16, 16, 16, __nv_bfloat16, wmma::row_major> ABf;
typedef wmma::fragment<wmma::matrix_b, 16, 16, 16, __nv_bfloat16, wmma::row_major> BBfR;
typedef wmma::fragment<wmma::accumulator, 16, 16, 16, float> CBf;

__device__ __forceinline__ void split2(float x, __nv_bfloat16& hi, __nv_bfloat16& lo) {
    hi = __float2bfloat16(x);
    lo = __float2bfloat16(x - __bfloat162float(hi));
}

// ---------------- cp.async helpers ----------------------------------------
__device__ __forceinline__ void cp16(uint32_t saddr, const void* gaddr) {
    asm volatile("cp.async.cg.shared.global [%0], [%1], 16;\n" :: "r"(saddr), "l"(gaddr));
}
#define CP_COMMIT() asm volatile("cp.async.commit_group;\n" ::: "memory")
#define CP_WAIT1()  asm volatile("cp.async.wait_group 1;\n" ::: "memory")
#define CP_WAIT0()  asm volatile("cp.async.wait_group 0;\n" ::: "memory")

__device__ __forceinline__ uint32_t smem_u32(const void* p) {
    uint32_t a;
    asm("{ .reg .u64 t; cvta.to.shared.u64 t, %1; cvt.u32.u64 %0, t; }" : "=r"(a) : "l"(p));
    return a;
}

// ---------------- raw mma helpers (attn) -----------------------------------
__device__ __forceinline__ void ldsm4(uint32_t& r0, uint32_t& r1, uint32_t& r2, uint32_t& r3, uint32_t a) {
    asm volatile("ldmatrix.sync.aligned.m8n8.x4.shared.b16 {%0,%1,%2,%3}, [%4];"
                 : "=r"(r0), "=r"(r1), "=r"(r2), "=r"(r3) : "r"(a));
}
__device__ __forceinline__ void ldsm4t(uint32_t& r0, uint32_t& r1, uint32_t& r2, uint32_t& r3, uint32_t a) {
    asm volatile("ldmatrix.sync.aligned.m8n8.x4.trans.shared.b16 {%0,%1,%2,%3}, [%4];"
                 : "=r"(r0), "=r"(r1), "=r"(r2), "=r"(r3) : "r"(a));
}
__device__ __forceinline__ void mma16816(float* d, const uint32_t* a, uint32_t b0, uint32_t b1) {
    asm volatile("mma.sync.aligned.m16n8k16.row.col.f32.bf16.bf16.f32 "
                 "{%0,%1,%2,%3}, {%4,%5,%6,%7}, {%8,%9}, {%0,%1,%2,%3};"
                 : "+f"(d[0]), "+f"(d[1]), "+f"(d[2]), "+f"(d[3])
                 : "r"(a[0]), "r"(a[1]), "r"(a[2]), "r"(a[3]), "r"(b0), "r"(b1));
}
// pack (c0 -> low bf16, c1 -> high bf16); lo gets the residual pair
__device__ __forceinline__ uint32_t packsplit(float c0, float c1, uint32_t& lo) {
    uint32_t hp;
    asm("cvt.rn.bf16x2.f32 %0, %1, %2;" : "=r"(hp) : "f"(c1), "f"(c0));
    __nv_bfloat162 hb = *reinterpret_cast<__nv_bfloat162*>(&hp);
    float2 hf = __bfloat1622float2(hb);          // .x = low(c0 part), .y = high
    uint32_t lp;
    asm("cvt.rn.bf16x2.f32 %0, %1, %2;" : "=r"(lp) : "f"(c1 - hf.y), "f"(c0 - hf.x));
    lo = lp;
    return hp;
}

#define LDB16 72   // wmma bf16 tile stride
#define LDF32 68   // wmma f32 tile stride

// ==========================================================================
// K0: presplit all f32 operands to bf16 hi/lo. (R8, passing)
// ==========================================================================
__global__ __launch_bounds__(256) void presplit_kernel(
    const float* __restrict__ q, const float* __restrict__ k, const float* __restrict__ v,
    const float* __restrict__ Wq, const float* __restrict__ Wk, const float* __restrict__ Wv,
    const float* __restrict__ Wo)
{
    int blk = blockIdx.x;
    const float* src; __nv_bfloat16 *hi, *lo; int base;
    if      (blk < 1024) { src = q;  hi = iq_hi; lo = iq_lo; base = blk; }
    else if (blk < 2048) { src = k;  hi = ik_hi; lo = ik_lo; base = blk - 1024; }
    else if (blk < 3072) { src = v;  hi = iv_hi; lo = iv_lo; base = blk - 2048; }
    else if (blk < 3328) { src = Wq; hi = wq_hi; lo = wq_lo; base = blk - 3072; }
    else if (blk < 3584) { src = Wk; hi = wk_hi; lo = wk_lo; base = blk - 3328; }
    else if (blk < 3840) { src = Wv; hi = wv_hi; lo = wv_lo; base = blk - 3584; }
    else                 { src = Wo; hi = wo_hi; lo = wo_lo; base = blk - 3840; }

#pragma unroll
    for (int j = 0; j < 4; j++) {
        size_t i4 = (size_t)base * 1024 + j * 256 + threadIdx.x;
        float4 val = ((const float4*)src)[i4];
        __nv_bfloat16 h0,h1,h2,h3,l0,l1,l2,l3;
        split2(val.x, h0, l0); split2(val.y, h1, l1);
        split2(val.z, h2, l2); split2(val.w, h3, l3);
        ((__nv_bfloat162*)hi)[i4*2]   = __halves2bfloat162(h0, h1);
        ((__nv_bfloat162*)hi)[i4*2+1] = __halves2bfloat162(h2, h3);
        ((__nv_bfloat162*)lo)[i4*2]   = __halves2bfloat162(l0, l1);
        ((__nv_bfloat162*)lo)[i4*2+1] = __halves2bfloat162(l2, l3);
    }
}

// ==========================================================================
// K1: fused QKV projection (wmma, R8 passing). grid (32, 48), 256 thr, 2/SM.
// ==========================================================================
__global__ __launch_bounds__(256, 2) void proj_kernel()
{
    extern __shared__ char smraw[];
    __nv_bfloat16* sAhi = (__nv_bfloat16*)smraw;
    __nv_bfloat16* sAlo = sAhi + 128 * LDB16;
    __nv_bfloat16* sBhi = sAlo + 128 * LDB16;
    __nv_bfloat16* sBlo = sBhi + 64 * LDB16;

    const int pz = blockIdx.y >> 4;
    const int h  = blockIdx.y & 15;
    const __nv_bfloat16* Xhi = (pz == 0) ? iq_hi : (pz == 1) ? ik_hi : iv_hi;
    const __nv_bfloat16* Xlo = (pz == 0) ? iq_lo : (pz == 1) ? ik_lo : iv_lo;
    const __nv_bfloat16* Whi = ((pz == 0) ? wq_hi : (pz == 1) ? wk_hi : wv_hi) + (size_t)h * HID * D_;
    const __nv_bfloat16* Wlo = ((pz == 0) ? wq_lo : (pz == 1) ? wk_lo : wv_lo) + (size_t)h * HID * D_;
    __nv_bfloat16* Ohi = (pz == 0) ? pq_hi : (pz == 1) ? pk_hi : pv_hi;
    __nv_bfloat16* Olo = (pz == 0) ? pq_lo : (pz == 1) ? pk_lo : pv_lo;

    const int m0   = blockIdx.x * 128;
    const int tid  = threadIdx.x;
    const int warp = tid >> 5;
    const int wm   = warp & 3;
    const int wn   = warp >> 2;

    CBf acc[2][2];
#pragma unroll
    for (int i = 0; i < 2; i++)
#pragma unroll
        for (int j = 0; j < 2; j++) wmma::fill_fragment(acc[i][j], 0.0f);

    for (int k0 = 0; k0 < HID; k0 += 64) {
#pragma unroll
        for (int i = tid; i < 1024; i += 256) {
            int r = i >> 3, c8 = (i & 7) * 8;
            size_t g = (size_t)(m0 + r) * HID + k0 + c8;
            *(uint4*)&sAhi[r * LDB16 + c8] = *(const uint4*)&Xhi[g];
            *(uint4*)&sAlo[r * LDB16 + c8] = *(const uint4*)&Xlo[g];
        }
#pragma unroll
        for (int i = tid; i < 512; i += 256) {
            int r = i >> 3, c8 = (i & 7) * 8;
            size_t g = (size_t)(k0 + r) * D_ + c8;
            *(uint4*)&sBhi[r * LDB16 + c8] = *(const uint4*)&Whi[g];
            *(uint4*)&sBlo[r * LDB16 + c8] = *(const uint4*)&Wlo[g];
        }
        __syncthreads();

#pragma unroll
        for (int kk = 0; kk < 4; kk++) {
            ABf ahi[2], alo[2];
#pragma unroll
            for (int i = 0; i < 2; i++) {
                wmma::load_matrix_sync(ahi[i], sAhi + (wm * 32 + i * 16) * LDB16 + kk * 16, LDB16);
                wmma::load_matrix_sync(alo[i], sAlo + (wm * 32 + i * 16) * LDB16 + kk * 16, LDB16);
            }
#pragma unroll
            for (int j = 0; j < 2; j++) {
                BBfR bhi, blo;
                wmma::load_matrix_sync(bhi, sBhi + (kk * 16) * LDB16 + wn * 32 + j * 16, LDB16);
                wmma::load_matrix_sync(blo, sBlo + (kk * 16) * LDB16 + wn * 32 + j * 16, LDB16);
#pragma unroll
                for (int i = 0; i < 2; i++) {
                    wmma::mma_sync(acc[i][j], ahi[i], bhi, acc[i][j]);
                    wmma::mma_sync(acc[i][j], ahi[i], blo, acc[i][j]);
                    wmma::mma_sync(acc[i][j], alo[i], bhi, acc[i][j]);
                }
            }
        }
        __syncthreads();
    }

    float* stage = (float*)smraw;
#pragma unroll
    for (int i = 0; i < 2; i++)
#pragma unroll
        for (int j = 0; j < 2; j++)
            wmma::store_matrix_sync(stage + (size_t)(wm * 32 + i * 16) * LDF32 + wn * 32 + j * 16,
                                    acc[i][j], LDF32, wmma::mem_row_major);
    __syncthreads();

    const int b  = m0 >> 11;
    const int s0 = m0 & (S_ - 1);
    const size_t orow0 = ((size_t)(b * H_ + h) * S_ + s0);
#pragma unroll
    for (int i = tid; i < 128 * 32; i += 256) {
        int r = i >> 5, c2 = (i & 31) * 2;
        float v0 = stage[r * LDF32 + c2], v1 = stage[r * LDF32 + c2 + 1];
        __nv_bfloat16 h0,h1,l0,l1;
        split2(v0, h0, l0); split2(v1, h1, l1);
        size_t g = (orow0 + r) * D_ + c2;
        *(__nv_bfloat162*)&Ohi[g] = __halves2bfloat162(h0, h1);
        *(__nv_bfloat162*)&Olo[g] = __halves2bfloat162(l0, l1);
    }
}

// ==========================================================================
// K2: attention, raw mma.sync.m16n8k16, register-resident P.
// grid (16, 32), 256 threads (8 warps). Warp w owns q-rows [w*16, w*16+16).
// Chunk = 64 KV tokens, 32 chunks, cp.async double-buffered.
// S acc: 8 x (16x8) tiles over 64 cols. P: acc->A-frag conversion in regs.
// O acc: 8 x (16x8) tiles over 64 dims, persistent. Rowsums in 2 regs.
// ==========================================================================
#define ATB 64
#define ANCH (S_/ATB)          // 32
#define KVLD 72                // padded row stride (elems)
#define AARR (ATB*KVLD)        // 4608 elems per array
#define ABUF (4*AARR)          // K hi | K lo | V hi | V lo
#define ATTN_SMEM (2*ABUF*2)   // 73728 bytes

__global__ __launch_bounds__(256) void attn_kernel(float* __restrict__ attn_out)
{
    extern __shared__ __nv_bfloat16 skv[];
    const int bh = blockIdx.y, qb = blockIdx.x;
    const int tid = threadIdx.x, w = tid >> 5, lane = tid & 31;
    const int g = lane >> 2, t = lane & 3;
    const size_t qrow0 = (size_t)bh * S_ + (size_t)qb * 128;
    const size_t krow0 = (size_t)bh * S_;
    const int wrow = w * 16;

    // ---- persistent Q fragments (direct LDG; A-frag layout) ----
    uint32_t qh[4][4], ql[4][4];
    {
        const __nv_bfloat16* Qh = pq_hi + (qrow0 + wrow) * D_;
        const __nv_bfloat16* Ql = pq_lo + (qrow0 + wrow) * D_;
#pragma unroll
        for (int ks = 0; ks < 4; ks++) {
            int c0 = ks * 16 + 2 * t;
            qh[ks][0] = *(const uint32_t*)&Qh[(size_t)g * D_ + c0];
            qh[ks][1] = *(const uint32_t*)&Qh[(size_t)(g + 8) * D_ + c0];
            qh[ks][2] = *(const uint32_t*)&Qh[(size_t)g * D_ + c0 + 8];
            qh[ks][3] = *(const uint32_t*)&Qh[(size_t)(g + 8) * D_ + c0 + 8];
            ql[ks][0] = *(const uint32_t*)&Ql[(size_t)g * D_ + c0];
            ql[ks][1] = *(const uint32_t*)&Ql[(size_t)(g + 8) * D_ + c0];
            ql[ks][2] = *(const uint32_t*)&Ql[(size_t)g * D_ + c0 + 8];
            ql[ks][3] = *(const uint32_t*)&Ql[(size_t)(g + 8) * D_ + c0 + 8];
        }
    }

    // ---- cp.async slot: each thread owns one KV row of one array ----
    const int arr = tid >> 6, rr = tid & 63;
    const __nv_bfloat16* mysrc = (arr == 0) ? pk_hi : (arr == 1) ? pk_lo
                               : (arr == 2) ? pv_hi : pv_lo;
    const uint32_t sbase = smem_u32(skv);
    const uint32_t myslot = (uint32_t)((arr * AARR + rr * KVLD) * 2);

    // prefetch chunk 0 -> buffer 0
    {
        const __nv_bfloat16* src = mysrc + (krow0 + rr) * D_;
        uint32_t dst = sbase + myslot;
#pragma unroll
        for (int s8 = 0; s8 < 8; s8++) cp16(dst + s8 * 16, src + s8 * 8);
        CP_COMMIT();
    }

    // ldmatrix lane offsets
    const int kr    = (lane & 7) + ((lane & 16) ? 8 : 0);   // K: row within 16-group
    const int khalf = ((lane >> 3) & 1) * 8;                // K: k-half
    const int vr    = (lane & 7) + (((lane >> 3) & 1) * 8); // V: token within kstep
    const int vcol  = (lane & 16) ? 8 : 0;                  // V: dim-half

    float accO[8][4];
#pragma unroll
    for (int j = 0; j < 8; j++)
#pragma unroll
        for (int e = 0; e < 4; e++) accO[j][e] = 0.0f;
    float rl = 0.0f, rh = 0.0f;

    for (int ch = 0; ch < ANCH; ch++) {
        __syncthreads();   // all warps done reading the buffer we're about to refill
        if (ch + 1 < ANCH) {
            const __nv_bfloat16* src = mysrc + (krow0 + (size_t)(ch + 1) * ATB + rr) * D_;
            uint32_t dst = sbase + (uint32_t)(((ch + 1) & 1) * ABUF * 2) + myslot;
#pragma unroll
            for (int s8 = 0; s8 < 8; s8++) cp16(dst + s8 * 16, src + s8 * 8);
            CP_COMMIT();
            CP_WAIT1();
        } else {
            CP_WAIT0();
        }
        __syncthreads();   // current buffer visible to all warps

        const uint32_t bufb = sbase + (uint32_t)((ch & 1) * ABUF * 2);
        const uint32_t kHiB = bufb;
        const uint32_t kLoB = bufb + AARR * 2;
        const uint32_t vHiB = bufb + 2 * AARR * 2;
        const uint32_t vLoB = bufb + 3 * AARR * 2;

        // ---- S = Q K^T (3-term) ----
        float accS[8][4];
#pragma unroll
        for (int j = 0; j < 8; j++)
#pragma unroll
            for (int e = 0; e < 4; e++) accS[j][e] = 0.0f;

#pragma unroll
        for (int ks = 0; ks < 4; ks++) {
#pragma unroll
            for (int j = 0; j < 4; j++) {
                uint32_t koff = (uint32_t)(((16 * j + kr) * KVLD + ks * 16 + khalf) * 2);
                uint32_t h0, h1, h2, h3, l0, l1, l2, l3;
                ldsm4(h0, h1, h2, h3, kHiB + koff);
                ldsm4(l0, l1, l2, l3, kLoB + koff);
                mma16816(accS[2 * j],     qh[ks], h0, h1);
                mma16816(accS[2 * j],     qh[ks], l0, l1);
                mma16816(accS[2 * j],     ql[ks], h0, h1);
                mma16816(accS[2 * j + 1], qh[ks], h2, h3);
                mma16816(accS[2 * j + 1], qh[ks], l2, l3);
                mma16816(accS[2 * j + 1], ql[ks], h2, h3);
            }
        }

        // ---- exp, unnormalized attn write, rowsum ----
#pragma unroll
        for (int j = 0; j < 8; j++) {
            float e0 = __expf(accS[j][0] * 0.125f);
            float e1 = __expf(accS[j][1] * 0.125f);
            float e2 = __expf(accS[j][2] * 0.125f);
            float e3 = __expf(accS[j][3] * 0.125f);
            accS[j][0] = e0; accS[j][1] = e1; accS[j][2] = e2; accS[j][3] = e3;
            rl += e0 + e1;
            rh += e2 + e3;
            if (attn_out) {
                size_t col = (size_t)ch * ATB + j * 8 + 2 * t;
                *(float2*)&attn_out[(qrow0 + wrow + g) * S_ + col]     = make_float2(e0, e1);
                *(float2*)&attn_out[(qrow0 + wrow + 8 + g) * S_ + col] = make_float2(e2, e3);
            }
        }

        // ---- O += P V (3-term), P built from accS in registers ----
#pragma unroll
        for (int ks = 0; ks < 4; ks++) {
            uint32_t pah[4], pal[4];
            pah[0] = packsplit(accS[2 * ks][0],     accS[2 * ks][1],     pal[0]);
            pah[1] = packsplit(accS[2 * ks][2],     accS[2 * ks][3],     pal[1]);
            pah[2] = packsplit(accS[2 * ks + 1][0], accS[2 * ks + 1][1], pal[2]);
            pah[3] = packsplit(accS[2 * ks + 1][2], accS[2 * ks + 1][3], pal[3]);
#pragma unroll
            for (int j = 0; j < 4; j++) {
                uint32_t voff = (uint32_t)(((ks * 16 + vr) * KVLD + 16 * j + vcol) * 2);
                uint32_t h0, h1, h2, h3, l0, l1, l2, l3;
                ldsm4t(h0, h1, h2, h3, vHiB + voff);
                ldsm4t(l0, l1, l2, l3, vLoB + voff);
                mma16816(accO[2 * j],     pah, h0, h1);
                mma16816(accO[2 * j],     pah, l0, l1);
                mma16816(accO[2 * j],     pal, h0, h1);
                mma16816(accO[2 * j + 1], pah, h2, h3);
                mma16816(accO[2 * j + 1], pah, l2, l3);
                mma16816(accO[2 * j + 1], pal, h2, h3);
            }
        }
    }

    // ---- rowsum reduce across t (lanes sharing a row) ----
    rl += __shfl_xor_sync(0xffffffffu, rl, 1);
    rl += __shfl_xor_sync(0xffffffffu, rl, 2);
    rh += __shfl_xor_sync(0xffffffffu, rh, 1);
    rh += __shfl_xor_sync(0xffffffffu, rh, 2);
    const float invl = 1.0f / rl, invh = 1.0f / rh;
    if (t == 0) {
        g_invsum[qrow0 + wrow + g]     = invl;
        g_invsum[qrow0 + wrow + 8 + g] = invh;
    }

    // ---- O epilogue: scale + split into concat layout ----
    const int b = bh >> 4, h = bh & 15;
    const size_t rowg = (size_t)b * S_ + (size_t)qb * 128 + wrow + g;
#pragma unroll
    for (int j = 0; j < 8; j++) {
        int col = h * D_ + j * 8 + 2 * t;
        float o0 = accO[j][0] * invl, o1 = accO[j][1] * invl;
        float o2 = accO[j][2] * invh, o3 = accO[j][3] * invh;
        __nv_bfloat16 h0, h1, l0, l1;
        split2(o0, h0, l0); split2(o1, h1, l1);
        *(__nv_bfloat162*)&cat_hi[rowg * HID + col] = __halves2bfloat162(h0, h1);
        *(__nv_bfloat162*)&cat_lo[rowg * HID + col] = __halves2bfloat162(l0, l1);
        split2(o2, h0, l0); split2(o3, h1, l1);
        *(__nv_bfloat162*)&cat_hi[(rowg + 8) * HID + col] = __halves2bfloat162(h0, h1);
        *(__nv_bfloat162*)&cat_lo[(rowg + 8) * HID + col] = __halves2bfloat162(l0, l1);
    }
}

// ==========================================================================
// K3: FUSED out-projection + attn normalization (R8 passing, parity).
// ==========================================================================
__global__ __launch_bounds__(256, 2) void outproj_scale_kernel(
    float* __restrict__ out, float* __restrict__ attn_out)
{
    const int bx  = blockIdx.x;
    const int idx = bx >> 1;
    const int tid = threadIdx.x;

    if (bx & 1) {
        if (!attn_out) return;
        const size_t row0 = (size_t)idx * 128;
        float4* p = (float4*)(attn_out + row0 * S_);
#pragma unroll 4
        for (int i = tid; i < 128 * (S_ / 4); i += 256) {
            float inv = g_invsum[row0 + (i >> 9)];
            float4 v = p[i];
            v.x *= inv; v.y *= inv; v.z *= inv; v.w *= inv;
            p[i] = v;
        }
        return;
    }

    extern __shared__ char smraw[];
    __nv_bfloat16* sAhi = (__nv_bfloat16*)smraw;
    __nv_bfloat16* sAlo = sAhi + 128 * LDB16;
    __nv_bfloat16* sBhi = sAlo + 128 * LDB16;
    __nv_bfloat16* sBlo = sBhi + 64 * LDB16;

    const int m0 = (idx & 31) * 128;
    const int n0 = (idx >> 5) * 64;
    const int warp = tid >> 5;
    const int wm = warp & 3;
    const int wn = warp >> 2;

    CBf acc[2][2];
#pragma unroll
    for (int i = 0; i < 2; i++)
#pragma unroll
        for (int j = 0; j < 2; j++) wmma::fill_fragment(acc[i][j], 0.0f);

    for (int k0 = 0; k0 < HID; k0 += 64) {
#pragma unroll
        for (int i = tid; i < 1024; i += 256) {
            int r = i >> 3, c8 = (i & 7) * 8;
            size_t g = (size_t)(m0 + r) * HID + k0 + c8;
            *(uint4*)&sAhi[r * LDB16 + c8] = *(const uint4*)&cat_hi[g];
            *(uint4*)&sAlo[r * LDB16 + c8] = *(const uint4*)&cat_lo[g];
        }
#pragma unroll
        for (int i = tid; i < 512; i += 256) {
            int r = i >> 3, c8 = (i & 7) * 8;
            size_t g = (size_t)(k0 + r) * HID + n0 + c8;
            *(uint4*)&sBhi[r * LDB16 + c8] = *(const uint4*)&wo_hi[g];
            *(uint4*)&sBlo[r * LDB16 + c8] = *(const uint4*)&wo_lo[g];
        }
        __syncthreads();

#pragma unroll
        for (int kk = 0; kk < 4; kk++) {
            ABf ahi[2], alo[2];
#pragma unroll
            for (int i = 0; i < 2; i++) {
                wmma::load_matrix_sync(ahi[i], sAhi + (wm * 32 + i * 16) * LDB16 + kk * 16, LDB16);
                wmma::load_matrix_sync(alo[i], sAlo + (wm * 32 + i * 16) * LDB16 + kk * 16, LDB16);
            }
#pragma unroll
            for (int j = 0; j < 2; j++) {
                BBfR bhi, blo;
                wmma::load_matrix_sync(bhi, sBhi + (kk * 16) * LDB16 + wn * 32 + j * 16, LDB16);
                wmma::load_matrix_sync(blo, sBlo + (kk * 16) * LDB16 + wn * 32 + j * 16, LDB16);
#pragma unroll
                for (int i = 0; i < 2; i++) {
                    wmma::mma_sync(acc[i][j], ahi[i], bhi, acc[i][j]);
                    wmma::mma_sync(acc[i][j], ahi[i], blo, acc[i][j]);
                    wmma::mma_sync(acc[i][j], alo[i], bhi, acc[i][j]);
                }
            }
        }
        __syncthreads();
    }

    float* obase = out + (size_t)m0 * HID + n0;
#pragma unroll
    for (int i = 0; i < 2; i++)
#pragma unroll
        for (int j = 0; j < 2; j++)
            wmma::store_matrix_sync(obase + (size_t)(wm * 32 + i * 16) * HID + wn * 32 + j * 16,
                                    acc[i][j], HID, wmma::mem_row_major);
}

// ==========================================================================
extern "C" void kernel_launch(void* const* d_in, const int* in_sizes, int n_in,
                              void* d_out, int out_size)
{
    const float* q  = (const float*)d_in[0];
    const float* k  = (const float*)d_in[1];
    const float* v  = (const float*)d_in[2];
    const float* Wq = (const float*)d_in[3];
    const float* Wk = (const float*)d_in[4];
    const float* Wv = (const float*)d_in[5];
    const float* Wo = (const float*)d_in[6];

    float* out  = (float*)d_out;
    float* attn = nullptr;
    const long long OUT_ELEMS  = (long long)MROWS * HID;
    const long long ATTN_ELEMS = (long long)B_ * H_ * S_ * S_;
    if ((long long)out_size >= OUT_ELEMS + ATTN_ELEMS)
        attn = out + OUT_ELEMS;

    const int gemm_smem = (128 + 64) * LDB16 * 2 * 2;        // 55296 bytes
    cudaFuncSetAttribute(proj_kernel,          cudaFuncAttributeMaxDynamicSharedMemorySize, gemm_smem);
    cudaFuncSetAttribute(outproj_scale_kernel, cudaFuncAttributeMaxDynamicSharedMemorySize, gemm_smem);
    cudaFuncSetAttribute(attn_kernel,          cudaFuncAttributeMaxDynamicSharedMemorySize, ATTN_SMEM);

    presplit_kernel<<<4096, 256>>>(q, k, v, Wq, Wk, Wv, Wo);

    dim3 g1(MROWS / 128, 3 * H_);
    proj_kernel<<<g1, 256, gemm_smem>>>();

    dim3 g2(S_ / 128, B_ * H_);
    attn_kernel<<<g2, 256, ATTN_SMEM>>>(attn);

    outproj_scale_kernel<<<1024, 256, gemm_smem>>>(out, attn);
}

// round 13
// speedup vs baseline: 4.3207x; 1.0141x over previous
#include <cuda_runtime.h>
#include <cuda_bf16.h>
#include <mma.h>
#include <cstdint>
#include <cstddef>

using namespace nvcuda;

#define B_   2
#define S_   2048
#define H_   16
#define D_   64
#define HID  1024
#define MROWS (B_*S_)          // 4096
#define XN (MROWS*HID)         // 4,194,304
#define WN (H_*HID*D_)         // 1,048,576

// ---------------- global scratch (static; no allocations) -----------------
__device__ __nv_bfloat16 iq_hi[XN], iq_lo[XN], ik_hi[XN], ik_lo[XN], iv_hi[XN], iv_lo[XN];
__device__ __nv_bfloat16 wq_hi[WN], wq_lo[WN], wk_hi[WN], wk_lo[WN], wv_hi[WN], wv_lo[WN];
__device__ __nv_bfloat16 wo_hi[WN], wo_lo[WN];
__device__ __nv_bfloat16 pq_hi[XN], pq_lo[XN], pk_hi[XN], pk_lo[XN], pv_hi[XN], pv_lo[XN];
__device__ __nv_bfloat16 cat_hi[XN], cat_lo[XN];
__device__ float g_invsum[(size_t)B_*H_*S_];

// ---------------- wmma fragment types (proj / outproj) --------------------
typedef wmma::fragment<wmma::matrix_a, 16, 16, 16, __nv_bfloat16, wmma::row_major> ABf;
typedef wmma::fragment<wmma::matrix_b, 16, 16, 16, __nv_bfloat16, wmma::row_major> BBfR;
typedef wmma::fragment<wmma::accumulator, 16, 16, 16, float> CBf;

__device__ __forceinline__ void split2(float x, __nv_bfloat16& hi, __nv_bfloat16& lo) {
    hi = __float2bfloat16(x);
    lo = __float2bfloat16(x - __bfloat162float(hi));
}

// ---------------- cp.async helpers ----------------------------------------
__device__ __forceinline__ void cp16(uint32_t saddr, const void* gaddr) {
    asm volatile("cp.async.cg.shared.global [%0], [%1], 16;\n" :: "r"(saddr), "l"(gaddr));
}
#define CP_COMMIT() asm volatile("cp.async.commit_group;\n" ::: "memory")
#define CP_WAIT1()  asm volatile("cp.async.wait_group 1;\n" ::: "memory")
#define CP_WAIT0()  asm volatile("cp.async.wait_group 0;\n" ::: "memory")

__device__ __forceinline__ uint32_t smem_u32(const void* p) {
    uint32_t a;
    asm("{ .reg .u64 t; cvta.to.shared.u64 t, %1; cvt.u32.u64 %0, t; }" : "=r"(a) : "l"(p));
    return a;
}

// ---------------- raw mma helpers (attn) -----------------------------------
__device__ __forceinline__ void ldsm4(uint32_t& r0, uint32_t& r1, uint32_t& r2, uint32_t& r3, uint32_t a) {
    asm volatile("ldmatrix.sync.aligned.m8n8.x4.shared.b16 {%0,%1,%2,%3}, [%4];"
                 : "=r"(r0), "=r"(r1), "=r"(r2), "=r"(r3) : "r"(a));
}
__device__ __forceinline__ void ldsm4t(uint32_t& r0, uint32_t& r1, uint32_t& r2, uint32_t& r3, uint32_t a) {
    asm volatile("ldmatrix.sync.aligned.m8n8.x4.trans.shared.b16 {%0,%1,%2,%3}, [%4];"
                 : "=r"(r0), "=r"(r1), "=r"(r2), "=r"(r3) : "r"(a));
}
__device__ __forceinline__ void mma16816(float* d, const uint32_t* a, uint32_t b0, uint32_t b1) {
    asm volatile("mma.sync.aligned.m16n8k16.row.col.f32.bf16.bf16.f32 "
                 "{%0,%1,%2,%3}, {%4,%5,%6,%7}, {%8,%9}, {%0,%1,%2,%3};"
                 : "+f"(d[0]), "+f"(d[1]), "+f"(d[2]), "+f"(d[3])
                 : "r"(a[0]), "r"(a[1]), "r"(a[2]), "r"(a[3]), "r"(b0), "r"(b1));
}
// pack (c0 -> low bf16, c1 -> high bf16); lo gets the residual pair
__device__ __forceinline__ uint32_t packsplit(float c0, float c1, uint32_t& lo) {
    uint32_t hp;
    asm("cvt.rn.bf16x2.f32 %0, %1, %2;" : "=r"(hp) : "f"(c1), "f"(c0));
    __nv_bfloat162 hb = *reinterpret_cast<__nv_bfloat162*>(&hp);
    float2 hf = __bfloat1622float2(hb);
    uint32_t lp;
    asm("cvt.rn.bf16x2.f32 %0, %1, %2;" : "=r"(lp) : "f"(c1 - hf.y), "f"(c0 - hf.x));
    lo = lp;
    return hp;
}

#define LDB16 72   // wmma bf16 tile stride
#define LDF32 68   // wmma f32 tile stride

// ==========================================================================
// K0: presplit all f32 operands to bf16 hi/lo. (passing)
// ==========================================================================
__global__ __launch_bounds__(256) void presplit_kernel(
    const float* __restrict__ q, const float* __restrict__ k, const float* __restrict__ v,
    const float* __restrict__ Wq, const float* __restrict__ Wk, const float* __restrict__ Wv,
    const float* __restrict__ Wo)
{
    int blk = blockIdx.x;
    const float* src; __nv_bfloat16 *hi, *lo; int base;
    if      (blk < 1024) { src = q;  hi = iq_hi; lo = iq_lo; base = blk; }
    else if (blk < 2048) { src = k;  hi = ik_hi; lo = ik_lo; base = blk - 1024; }
    else if (blk < 3072) { src = v;  hi = iv_hi; lo = iv_lo; base = blk - 2048; }
    else if (blk < 3328) { src = Wq; hi = wq_hi; lo = wq_lo; base = blk - 3072; }
    else if (blk < 3584) { src = Wk; hi = wk_hi; lo = wk_lo; base = blk - 3328; }
    else if (blk < 3840) { src = Wv; hi = wv_hi; lo = wv_lo; base = blk - 3584; }
    else                 { src = Wo; hi = wo_hi; lo = wo_lo; base = blk - 3840; }

#pragma unroll
    for (int j = 0; j < 4; j++) {
        size_t i4 = (size_t)base * 1024 + j * 256 + threadIdx.x;
        float4 val = ((const float4*)src)[i4];
        __nv_bfloat16 h0,h1,h2,h3,l0,l1,l2,l3;
        split2(val.x, h0, l0); split2(val.y, h1, l1);
        split2(val.z, h2, l2); split2(val.w, h3, l3);
        ((__nv_bfloat162*)hi)[i4*2]   = __halves2bfloat162(h0, h1);
        ((__nv_bfloat162*)hi)[i4*2+1] = __halves2bfloat162(h2, h3);
        ((__nv_bfloat162*)lo)[i4*2]   = __halves2bfloat162(l0, l1);
        ((__nv_bfloat162*)lo)[i4*2+1] = __halves2bfloat162(l2, l3);
    }
}

// ==========================================================================
// K1: fused QKV projection (wmma). Term-major MMA order (chain dist 4).
// grid (32, 48), 256 threads, 2 blocks/SM.
// ==========================================================================
__global__ __launch_bounds__(256, 2) void proj_kernel()
{
    extern __shared__ char smraw[];
    __nv_bfloat16* sAhi = (__nv_bfloat16*)smraw;
    __nv_bfloat16* sAlo = sAhi + 128 * LDB16;
    __nv_bfloat16* sBhi = sAlo + 128 * LDB16;
    __nv_bfloat16* sBlo = sBhi + 64 * LDB16;

    const int pz = blockIdx.y >> 4;
    const int h  = blockIdx.y & 15;
    const __nv_bfloat16* Xhi = (pz == 0) ? iq_hi : (pz == 1) ? ik_hi : iv_hi;
    const __nv_bfloat16* Xlo = (pz == 0) ? iq_lo : (pz == 1) ? ik_lo : iv_lo;
    const __nv_bfloat16* Whi = ((pz == 0) ? wq_hi : (pz == 1) ? wk_hi : wv_hi) + (size_t)h * HID * D_;
    const __nv_bfloat16* Wlo = ((pz == 0) ? wq_lo : (pz == 1) ? wk_lo : wv_lo) + (size_t)h * HID * D_;
    __nv_bfloat16* Ohi = (pz == 0) ? pq_hi : (pz == 1) ? pk_hi : pv_hi;
    __nv_bfloat16* Olo = (pz == 0) ? pq_lo : (pz == 1) ? pk_lo : pv_lo;

    const int m0   = blockIdx.x * 128;
    const int tid  = threadIdx.x;
    const int warp = tid >> 5;
    const int wm   = warp & 3;
    const int wn   = warp >> 2;

    CBf acc[2][2];
#pragma unroll
    for (int i = 0; i < 2; i++)
#pragma unroll
        for (int j = 0; j < 2; j++) wmma::fill_fragment(acc[i][j], 0.0f);

    for (int k0 = 0; k0 < HID; k0 += 64) {
#pragma unroll
        for (int i = tid; i < 1024; i += 256) {
            int r = i >> 3, c8 = (i & 7) * 8;
            size_t g = (size_t)(m0 + r) * HID + k0 + c8;
            *(uint4*)&sAhi[r * LDB16 + c8] = *(const uint4*)&Xhi[g];
            *(uint4*)&sAlo[r * LDB16 + c8] = *(const uint4*)&Xlo[g];
        }
#pragma unroll
        for (int i = tid; i < 512; i += 256) {
            int r = i >> 3, c8 = (i & 7) * 8;
            size_t g = (size_t)(k0 + r) * D_ + c8;
            *(uint4*)&sBhi[r * LDB16 + c8] = *(const uint4*)&Whi[g];
            *(uint4*)&sBlo[r * LDB16 + c8] = *(const uint4*)&Wlo[g];
        }
        __syncthreads();

#pragma unroll
        for (int kk = 0; kk < 4; kk++) {
            ABf ahi[2], alo[2];
            BBfR bhi[2], blo[2];
#pragma unroll
            for (int i = 0; i < 2; i++) {
                wmma::load_matrix_sync(ahi[i], sAhi + (wm * 32 + i * 16) * LDB16 + kk * 16, LDB16);
                wmma::load_matrix_sync(alo[i], sAlo + (wm * 32 + i * 16) * LDB16 + kk * 16, LDB16);
            }
#pragma unroll
            for (int j = 0; j < 2; j++) {
                wmma::load_matrix_sync(bhi[j], sBhi + (kk * 16) * LDB16 + wn * 32 + j * 16, LDB16);
                wmma::load_matrix_sync(blo[j], sBlo + (kk * 16) * LDB16 + wn * 32 + j * 16, LDB16);
            }
            // term-major: 4 independent accumulators per term
#pragma unroll
            for (int i = 0; i < 2; i++)
#pragma unroll
                for (int j = 0; j < 2; j++)
                    wmma::mma_sync(acc[i][j], ahi[i], bhi[j], acc[i][j]);
#pragma unroll
            for (int i = 0; i < 2; i++)
#pragma unroll
                for (int j = 0; j < 2; j++)
                    wmma::mma_sync(acc[i][j], ahi[i], blo[j], acc[i][j]);
#pragma unroll
            for (int i = 0; i < 2; i++)
#pragma unroll
                for (int j = 0; j < 2; j++)
                    wmma::mma_sync(acc[i][j], alo[i], bhi[j], acc[i][j]);
        }
        __syncthreads();
    }

    float* stage = (float*)smraw;
#pragma unroll
    for (int i = 0; i < 2; i++)
#pragma unroll
        for (int j = 0; j < 2; j++)
            wmma::store_matrix_sync(stage + (size_t)(wm * 32 + i * 16) * LDF32 + wn * 32 + j * 16,
                                    acc[i][j], LDF32, wmma::mem_row_major);
    __syncthreads();

    const int b  = m0 >> 11;
    const int s0 = m0 & (S_ - 1);
    const size_t orow0 = ((size_t)(b * H_ + h) * S_ + s0);
#pragma unroll
    for (int i = tid; i < 128 * 32; i += 256) {
        int r = i >> 5, c2 = (i & 31) * 2;
        float v0 = stage[r * LDF32 + c2], v1 = stage[r * LDF32 + c2 + 1];
        __nv_bfloat16 h0,h1,l0,l1;
        split2(v0, h0, l0); split2(v1, h1, l1);
        size_t g = (orow0 + r) * D_ + c2;
        *(__nv_bfloat162*)&Ohi[g] = __halves2bfloat162(h0, h1);
        *(__nv_bfloat162*)&Olo[g] = __halves2bfloat162(l0, l1);
    }
}

// ==========================================================================
// K2: attention, raw mma.sync, register-resident P, TERM-MAJOR mma order.
// grid (16, 32), 256 threads (8 warps). Warp w owns q-rows [w*16, w*16+16).
// ==========================================================================
#define ATB 64
#define ANCH (S_/ATB)          // 32
#define KVLD 72
#define AARR (ATB*KVLD)        // 4608 elems per array
#define ABUF (4*AARR)
#define ATTN_SMEM (2*ABUF*2)   // 73728 bytes

__global__ __launch_bounds__(256) void attn_kernel(float* __restrict__ attn_out)
{
    extern __shared__ __nv_bfloat16 skv[];
    const int bh = blockIdx.y, qb = blockIdx.x;
    const int tid = threadIdx.x, w = tid >> 5, lane = tid & 31;
    const int g = lane >> 2, t = lane & 3;
    const size_t qrow0 = (size_t)bh * S_ + (size_t)qb * 128;
    const size_t krow0 = (size_t)bh * S_;
    const int wrow = w * 16;

    // ---- persistent Q fragments ----
    uint32_t qh[4][4], ql[4][4];
    {
        const __nv_bfloat16* Qh = pq_hi + (qrow0 + wrow) * D_;
        const __nv_bfloat16* Ql = pq_lo + (qrow0 + wrow) * D_;
#pragma unroll
        for (int ks = 0; ks < 4; ks++) {
            int c0 = ks * 16 + 2 * t;
            qh[ks][0] = *(const uint32_t*)&Qh[(size_t)g * D_ + c0];
            qh[ks][1] = *(const uint32_t*)&Qh[(size_t)(g + 8) * D_ + c0];
            qh[ks][2] = *(const uint32_t*)&Qh[(size_t)g * D_ + c0 + 8];
            qh[ks][3] = *(const uint32_t*)&Qh[(size_t)(g + 8) * D_ + c0 + 8];
            ql[ks][0] = *(const uint32_t*)&Ql[(size_t)g * D_ + c0];
            ql[ks][1] = *(const uint32_t*)&Ql[(size_t)(g + 8) * D_ + c0];
            ql[ks][2] = *(const uint32_t*)&Ql[(size_t)g * D_ + c0 + 8];
            ql[ks][3] = *(const uint32_t*)&Ql[(size_t)(g + 8) * D_ + c0 + 8];
        }
    }

    // ---- cp.async slot ----
    const int arr = tid >> 6, rr = tid & 63;
    const __nv_bfloat16* mysrc = (arr == 0) ? pk_hi : (arr == 1) ? pk_lo
                               : (arr == 2) ? pv_hi : pv_lo;
    const uint32_t sbase = smem_u32(skv);
    const uint32_t myslot = (uint32_t)((arr * AARR + rr * KVLD) * 2);

    {
        const __nv_bfloat16* src = mysrc + (krow0 + rr) * D_;
        uint32_t dst = sbase + myslot;
#pragma unroll
        for (int s8 = 0; s8 < 8; s8++) cp16(dst + s8 * 16, src + s8 * 8);
        CP_COMMIT();
    }

    const int kr    = (lane & 7) + ((lane & 16) ? 8 : 0);
    const int khalf = ((lane >> 3) & 1) * 8;
    const int vr    = (lane & 7) + (((lane >> 3) & 1) * 8);
    const int vcol  = (lane & 16) ? 8 : 0;

    float accO[8][4];
#pragma unroll
    for (int j = 0; j < 8; j++)
#pragma unroll
        for (int e = 0; e < 4; e++) accO[j][e] = 0.0f;
    float rl = 0.0f, rh = 0.0f;

    for (int ch = 0; ch < ANCH; ch++) {
        __syncthreads();
        if (ch + 1 < ANCH) {
            const __nv_bfloat16* src = mysrc + (krow0 + (size_t)(ch + 1) * ATB + rr) * D_;
            uint32_t dst = sbase + (uint32_t)(((ch + 1) & 1) * ABUF * 2) + myslot;
#pragma unroll
            for (int s8 = 0; s8 < 8; s8++) cp16(dst + s8 * 16, src + s8 * 8);
            CP_COMMIT();
            CP_WAIT1();
        } else {
            CP_WAIT0();
        }
        __syncthreads();

        const uint32_t bufb = sbase + (uint32_t)((ch & 1) * ABUF * 2);
        const uint32_t kHiB = bufb;
        const uint32_t kLoB = bufb + AARR * 2;
        const uint32_t vHiB = bufb + 2 * AARR * 2;
        const uint32_t vLoB = bufb + 3 * AARR * 2;

        // ---- S = Q K^T (3-term), term-major per ks ----
        float accS[8][4];
#pragma unroll
        for (int j = 0; j < 8; j++)
#pragma unroll
            for (int e = 0; e < 4; e++) accS[j][e] = 0.0f;

#pragma unroll
        for (int ks = 0; ks < 4; ks++) {
            uint32_t kh[4][4], kl[4][4];
#pragma unroll
            for (int j = 0; j < 4; j++) {
                uint32_t koff = (uint32_t)(((16 * j + kr) * KVLD + ks * 16 + khalf) * 2);
                ldsm4(kh[j][0], kh[j][1], kh[j][2], kh[j][3], kHiB + koff);
                ldsm4(kl[j][0], kl[j][1], kl[j][2], kl[j][3], kLoB + koff);
            }
            // term 1: qh x kh  (8 independent accumulators)
#pragma unroll
            for (int j = 0; j < 4; j++) {
                mma16816(accS[2 * j],     qh[ks], kh[j][0], kh[j][1]);
                mma16816(accS[2 * j + 1], qh[ks], kh[j][2], kh[j][3]);
            }
            // term 2: qh x kl
#pragma unroll
            for (int j = 0; j < 4; j++) {
                mma16816(accS[2 * j],     qh[ks], kl[j][0], kl[j][1]);
                mma16816(accS[2 * j + 1], qh[ks], kl[j][2], kl[j][3]);
            }
            // term 3: ql x kh
#pragma unroll
            for (int j = 0; j < 4; j++) {
                mma16816(accS[2 * j],     ql[ks], kh[j][0], kh[j][1]);
                mma16816(accS[2 * j + 1], ql[ks], kh[j][2], kh[j][3]);
            }
        }

        // ---- exp, unnormalized attn write, rowsum ----
#pragma unroll
        for (int j = 0; j < 8; j++) {
            float e0 = __expf(accS[j][0] * 0.125f);
            float e1 = __expf(accS[j][1] * 0.125f);
            float e2 = __expf(accS[j][2] * 0.125f);
            float e3 = __expf(accS[j][3] * 0.125f);
            accS[j][0] = e0; accS[j][1] = e1; accS[j][2] = e2; accS[j][3] = e3;
            rl += e0 + e1;
            rh += e2 + e3;
            if (attn_out) {
                size_t col = (size_t)ch * ATB + j * 8 + 2 * t;
                *(float2*)&attn_out[(qrow0 + wrow + g) * S_ + col]     = make_float2(e0, e1);
                *(float2*)&attn_out[(qrow0 + wrow + 8 + g) * S_ + col] = make_float2(e2, e3);
            }
        }

        // ---- O += P V (3-term), term-major per ks ----
#pragma unroll
        for (int ks = 0; ks < 4; ks++) {
            uint32_t pah[4], pal[4];
            pah[0] = packsplit(accS[2 * ks][0],     accS[2 * ks][1],     pal[0]);
            pah[1] = packsplit(accS[2 * ks][2],     accS[2 * ks][3],     pal[1]);
            pah[2] = packsplit(accS[2 * ks + 1][0], accS[2 * ks + 1][1], pal[2]);
            pah[3] = packsplit(accS[2 * ks + 1][2], accS[2 * ks + 1][3], pal[3]);
            uint32_t vh[4][4], vl[4][4];
#pragma unroll
            for (int j = 0; j < 4; j++) {
                uint32_t voff = (uint32_t)(((ks * 16 + vr) * KVLD + 16 * j + vcol) * 2);
                ldsm4t(vh[j][0], vh[j][1], vh[j][2], vh[j][3], vHiB + voff);
                ldsm4t(vl[j][0], vl[j][1], vl[j][2], vl[j][3], vLoB + voff);
            }
#pragma unroll
            for (int j = 0; j < 4; j++) {
                mma16816(accO[2 * j],     pah, vh[j][0], vh[j][1]);
                mma16816(accO[2 * j + 1], pah, vh[j][2], vh[j][3]);
            }
#pragma unroll
            for (int j = 0; j < 4; j++) {
                mma16816(accO[2 * j],     pah, vl[j][0], vl[j][1]);
                mma16816(accO[2 * j + 1], pah, vl[j][2], vl[j][3]);
            }
#pragma unroll
            for (int j = 0; j < 4; j++) {
                mma16816(accO[2 * j],     pal, vh[j][0], vh[j][1]);
                mma16816(accO[2 * j + 1], pal, vh[j][2], vh[j][3]);
            }
        }
    }

    // ---- rowsum reduce across t ----
    rl += __shfl_xor_sync(0xffffffffu, rl, 1);
    rl += __shfl_xor_sync(0xffffffffu, rl, 2);
    rh += __shfl_xor_sync(0xffffffffu, rh, 1);
    rh += __shfl_xor_sync(0xffffffffu, rh, 2);
    const float invl = 1.0f / rl, invh = 1.0f / rh;
    if (t == 0) {
        g_invsum[qrow0 + wrow + g]     = invl;
        g_invsum[qrow0 + wrow + 8 + g] = invh;
    }

    // ---- O epilogue ----
    const int b = bh >> 4, h = bh & 15;
    const size_t rowg = (size_t)b * S_ + (size_t)qb * 128 + wrow + g;
#pragma unroll
    for (int j = 0; j < 8; j++) {
        int col = h * D_ + j * 8 + 2 * t;
        float o0 = accO[j][0] * invl, o1 = accO[j][1] * invl;
        float o2 = accO[j][2] * invh, o3 = accO[j][3] * invh;
        __nv_bfloat16 h0, h1, l0, l1;
        split2(o0, h0, l0); split2(o1, h1, l1);
        *(__nv_bfloat162*)&cat_hi[rowg * HID + col] = __halves2bfloat162(h0, h1);
        *(__nv_bfloat162*)&cat_lo[rowg * HID + col] = __halves2bfloat162(l0, l1);
        split2(o2, h0, l0); split2(o3, h1, l1);
        *(__nv_bfloat162*)&cat_hi[(rowg + 8) * HID + col] = __halves2bfloat162(h0, h1);
        *(__nv_bfloat162*)&cat_lo[(rowg + 8) * HID + col] = __halves2bfloat162(l0, l1);
    }
}

// ==========================================================================
// K3: FUSED out-projection + attn normalization, parity, term-major MMA.
// ==========================================================================
__global__ __launch_bounds__(256, 2) void outproj_scale_kernel(
    float* __restrict__ out, float* __restrict__ attn_out)
{
    const int bx  = blockIdx.x;
    const int idx = bx >> 1;
    const int tid = threadIdx.x;

    if (bx & 1) {
        if (!attn_out) return;
        const size_t row0 = (size_t)idx * 128;
        float4* p = (float4*)(attn_out + row0 * S_);
#pragma unroll 4
        for (int i = tid; i < 128 * (S_ / 4); i += 256) {
            float inv = g_invsum[row0 + (i >> 9)];
            float4 v = p[i];
            v.x *= inv; v.y *= inv; v.z *= inv; v.w *= inv;
            p[i] = v;
        }
        return;
    }

    extern __shared__ char smraw[];
    __nv_bfloat16* sAhi = (__nv_bfloat16*)smraw;
    __nv_bfloat16* sAlo = sAhi + 128 * LDB16;
    __nv_bfloat16* sBhi = sAlo + 128 * LDB16;
    __nv_bfloat16* sBlo = sBhi + 64 * LDB16;

    const int m0 = (idx & 31) * 128;
    const int n0 = (idx >> 5) * 64;
    const int warp = tid >> 5;
    const int wm = warp & 3;
    const int wn = warp >> 2;

    CBf acc[2][2];
#pragma unroll
    for (int i = 0; i < 2; i++)
#pragma unroll
        for (int j = 0; j < 2; j++) wmma::fill_fragment(acc[i][j], 0.0f);

    for (int k0 = 0; k0 < HID; k0 += 64) {
#pragma unroll
        for (int i = tid; i < 1024; i += 256) {
            int r = i >> 3, c8 = (i & 7) * 8;
            size_t g = (size_t)(m0 + r) * HID + k0 + c8;
            *(uint4*)&sAhi[r * LDB16 + c8] = *(const uint4*)&cat_hi[g];
            *(uint4*)&sAlo[r * LDB16 + c8] = *(const uint4*)&cat_lo[g];
        }
#pragma unroll
        for (int i = tid; i < 512; i += 256) {
            int r = i >> 3, c8 = (i & 7) * 8;
            size_t g = (size_t)(k0 + r) * HID + n0 + c8;
            *(uint4*)&sBhi[r * LDB16 + c8] = *(const uint4*)&wo_hi[g];
            *(uint4*)&sBlo[r * LDB16 + c8] = *(const uint4*)&wo_lo[g];
        }
        __syncthreads();

#pragma unroll
        for (int kk = 0; kk < 4; kk++) {
            ABf ahi[2], alo[2];
            BBfR bhi[2], blo[2];
#pragma unroll
            for (int i = 0; i < 2; i++) {
                wmma::load_matrix_sync(ahi[i], sAhi + (wm * 32 + i * 16) * LDB16 + kk * 16, LDB16);
                wmma::load_matrix_sync(alo[i], sAlo + (wm * 32 + i * 16) * LDB16 + kk * 16, LDB16);
            }
#pragma unroll
            for (int j = 0; j < 2; j++) {
                wmma::load_matrix_sync(bhi[j], sBhi + (kk * 16) * LDB16 + wn * 32 + j * 16, LDB16);
                wmma::load_matrix_sync(blo[j], sBlo + (kk * 16) * LDB16 + wn * 32 + j * 16, LDB16);
            }
#pragma unroll
            for (int i = 0; i < 2; i++)
#pragma unroll
                for (int j = 0; j < 2; j++)
                    wmma::mma_sync(acc[i][j], ahi[i], bhi[j], acc[i][j]);
#pragma unroll
            for (int i = 0; i < 2; i++)
#pragma unroll
                for (int j = 0; j < 2; j++)
                    wmma::mma_sync(acc[i][j], ahi[i], blo[j], acc[i][j]);
#pragma unroll
            for (int i = 0; i < 2; i++)
#pragma unroll
                for (int j = 0; j < 2; j++)
                    wmma::mma_sync(acc[i][j], alo[i], bhi[j], acc[i][j]);
        }
        __syncthreads();
    }

    float* obase = out + (size_t)m0 * HID + n0;
#pragma unroll
    for (int i = 0; i < 2; i++)
#pragma unroll
        for (int j = 0; j < 2; j++)
            wmma::store_matrix_sync(obase + (size_t)(wm * 32 + i * 16) * HID + wn * 32 + j * 16,
                                    acc[i][j], HID, wmma::mem_row_major);
}

// ==========================================================================
extern "C" void kernel_launch(void* const* d_in, const int* in_sizes, int n_in,
                              void* d_out, int out_size)
{
    const float* q  = (const float*)d_in[0];
    const float* k  = (const float*)d_in[1];
    const float* v  = (const float*)d_in[2];
    const float* Wq = (const float*)d_in[3];
    const float* Wk = (const float*)d_in[4];
    const float* Wv = (const float*)d_in[5];
    const float* Wo = (const float*)d_in[6];

    float* out  = (float*)d_out;
    float* attn = nullptr;
    const long long OUT_ELEMS  = (long long)MROWS * HID;
    const long long ATTN_ELEMS = (long long)B_ * H_ * S_ * S_;
    if ((long long)out_size >= OUT_ELEMS + ATTN_ELEMS)
        attn = out + OUT_ELEMS;

    const int gemm_smem = (128 + 64) * LDB16 * 2 * 2;        // 55296 bytes
    cudaFuncSetAttribute(proj_kernel,          cudaFuncAttributeMaxDynamicSharedMemorySize, gemm_smem);
    cudaFuncSetAttribute(outproj_scale_kernel, cudaFuncAttributeMaxDynamicSharedMemorySize, gemm_smem);
    cudaFuncSetAttribute(attn_kernel,          cudaFuncAttributeMaxDynamicSharedMemorySize, ATTN_SMEM);

    presplit_kernel<<<4096, 256>>>(q, k, v, Wq, Wk, Wv, Wo);

    dim3 g1(MROWS / 128, 3 * H_);
    proj_kernel<<<g1, 256, gemm_smem>>>();

    dim3 g2(S_ / 128, B_ * H_);
    attn_kernel<<<g2, 256, ATTN_SMEM>>>(attn);

    outproj_scale_kernel<<<1024, 256, gemm_smem>>>(out, attn);
}